// round 1
// baseline (speedup 1.0000x reference)
#include <cuda_runtime.h>
#include <math.h>

// Problem constants
#define BB      16
#define GRID_D  1024
#define SEQ_D   1024
#define POS_D   512
#define NH      16
#define HEAD    64
#define LQ      1024
#define TKV     256
#define MULT    4
#define EPSF    1e-5f

// ---------------- scratch (static device memory; no runtime allocation) ---------------
__device__ float g_Kpre[(size_t)BB * TKV * SEQ_D];          // 16 MB
__device__ float g_Kn  [(size_t)BB * TKV * SEQ_D];          // 16 MB
__device__ float g_V   [(size_t)BB * TKV * SEQ_D];          // 16 MB
__device__ float g_qn  [(size_t)BB * LQ * POS_D];           // 32 MB
__device__ float g_Q   [(size_t)BB * LQ * SEQ_D];           // 64 MB
__device__ float g_S   [(size_t)BB * NH * LQ * TKV];        // 256 MB
__device__ float g_attn[(size_t)BB * LQ * SEQ_D];           // 64 MB
__device__ float g_x   [(size_t)BB * LQ * SEQ_D];           // 64 MB
__device__ float g_xn  [(size_t)BB * LQ * SEQ_D];           // 64 MB
__device__ float g_h   [(size_t)BB * LQ * MULT * SEQ_D];    // 256 MB

// ---------------- helpers ----------------
__device__ __forceinline__ float gelu_f(float v) {
    // jax.nn.gelu default (approximate=True): tanh approximation
    float v3 = v * v * v;
    return 0.5f * v * (1.0f + tanhf(0.7978845608028654f * (v + 0.044715f * v3)));
}

enum { EPI_NONE = 0, EPI_RESID = 1, EPI_GELU_BIAS = 2, EPI_BIAS_RESID = 3 };

// ---------------- generic tiled fp32 GEMM ----------------
// C[M,N] = alpha * A[M,K] @ B(K,N)  (+ epilogue)
// If TRB: B operand stored as Bm[n][k] (row-major with leading dim ldb), i.e. NT GEMM.
// Batched via blockIdx.z = bb*nh + hh with separate (b,h) strides per operand.
template <int EPI, bool TRB>
__global__ __launch_bounds__(256)
void gemm_kernel(const float* __restrict__ A, const float* __restrict__ Bm,
                 const float* __restrict__ bias, const float* __restrict__ res,
                 float* __restrict__ C,
                 int M, int N, int K, int lda, int ldb, int ldc,
                 long sAb, long sAh, long sBb, long sBh, long sCb, long sCh,
                 int nh, float alpha)
{
    constexpr int BM = 128, BN = 64, BK = 16;
    __shared__ float As[BK][BM];
    __shared__ float Bs[BK][BN];

    int z  = blockIdx.z;
    int zb = z / nh, zh = z % nh;
    A  += (size_t)zb * sAb + (size_t)zh * sAh;
    Bm += (size_t)zb * sBb + (size_t)zh * sBh;
    C  += (size_t)zb * sCb + (size_t)zh * sCh;
    if (EPI == EPI_RESID || EPI == EPI_BIAS_RESID)
        res += (size_t)zb * sCb + (size_t)zh * sCh;

    int tid = threadIdx.x;
    int tx = tid & 15, ty = tid >> 4;
    int m0 = blockIdx.y * BM, n0 = blockIdx.x * BN;

    float acc[8][4];
#pragma unroll
    for (int i = 0; i < 8; i++)
#pragma unroll
        for (int j = 0; j < 4; j++) acc[i][j] = 0.0f;

    for (int k0 = 0; k0 < K; k0 += BK) {
        // Load A tile (BM x BK), store transposed As[k][m]
#pragma unroll
        for (int i = 0; i < 2; i++) {
            int idx = tid + i * 256;        // 0..511
            int r   = idx >> 2;             // 0..127 (m within tile)
            int c4  = (idx & 3) << 2;       // 0,4,8,12 (k within tile)
            float4 v = *(const float4*)(A + (size_t)(m0 + r) * lda + k0 + c4);
            As[c4 + 0][r] = v.x; As[c4 + 1][r] = v.y;
            As[c4 + 2][r] = v.z; As[c4 + 3][r] = v.w;
        }
        // Load B tile (BK x BN)
        if (!TRB) {
            int r  = tid >> 4;              // k row 0..15
            int c4 = (tid & 15) << 2;       // n 0..60
            float4 v = *(const float4*)(Bm + (size_t)(k0 + r) * ldb + n0 + c4);
            *(float4*)&Bs[r][c4] = v;
        } else {
            int r  = tid >> 2;              // n row 0..63
            int c4 = (tid & 3) << 2;        // k 0,4,8,12
            float4 v = *(const float4*)(Bm + (size_t)(n0 + r) * ldb + k0 + c4);
            Bs[c4 + 0][r] = v.x; Bs[c4 + 1][r] = v.y;
            Bs[c4 + 2][r] = v.z; Bs[c4 + 3][r] = v.w;
        }
        __syncthreads();

#pragma unroll
        for (int k = 0; k < BK; k++) {
            float a[8], bf[4];
            *(float4*)&a[0] = *(const float4*)&As[k][ty * 8];
            *(float4*)&a[4] = *(const float4*)&As[k][ty * 8 + 4];
            *(float4*)&bf[0] = *(const float4*)&Bs[k][tx * 4];
#pragma unroll
            for (int i = 0; i < 8; i++)
#pragma unroll
                for (int j = 0; j < 4; j++)
                    acc[i][j] = fmaf(a[i], bf[j], acc[i][j]);
        }
        __syncthreads();
    }

    // Epilogue
    int c = n0 + tx * 4;
#pragma unroll
    for (int i = 0; i < 8; i++) {
        int r = m0 + ty * 8 + i;
        float4 v = make_float4(acc[i][0] * alpha, acc[i][1] * alpha,
                               acc[i][2] * alpha, acc[i][3] * alpha);
        if (EPI == EPI_GELU_BIAS) {
            float4 bv = *(const float4*)(bias + c);
            v.x = gelu_f(v.x + bv.x); v.y = gelu_f(v.y + bv.y);
            v.z = gelu_f(v.z + bv.z); v.w = gelu_f(v.w + bv.w);
        } else if (EPI == EPI_RESID) {
            float4 rv = *(const float4*)(res + (size_t)r * ldc + c);
            v.x += rv.x; v.y += rv.y; v.z += rv.z; v.w += rv.w;
        } else if (EPI == EPI_BIAS_RESID) {
            float4 bv = *(const float4*)(bias + c);
            float4 rv = *(const float4*)(res + (size_t)r * ldc + c);
            v.x += bv.x + rv.x; v.y += bv.y + rv.y;
            v.z += bv.z + rv.z; v.w += bv.w + rv.w;
        }
        *(float4*)(C + (size_t)r * ldc + c) = v;
    }
}

// ---------------- LayerNorm: one block per row ----------------
__global__ __launch_bounds__(256)
void ln_kernel(const float* __restrict__ X, const float* __restrict__ g,
               const float* __restrict__ b, float* __restrict__ Y, int D)
{
    long row = blockIdx.x;
    const float4* x4 = (const float4*)(X + row * (long)D);
    float4*       y4 = (float4*)(Y + row * (long)D);
    const float4* g4 = (const float4*)g;
    const float4* b4 = (const float4*)b;
    int n4 = D >> 2;

    float s = 0.0f, s2 = 0.0f;
    for (int i = threadIdx.x; i < n4; i += 256) {
        float4 v = x4[i];
        s  += v.x + v.y + v.z + v.w;
        s2 += v.x * v.x + v.y * v.y + v.z * v.z + v.w * v.w;
    }
#pragma unroll
    for (int o = 16; o; o >>= 1) {
        s  += __shfl_xor_sync(0xffffffffu, s, o);
        s2 += __shfl_xor_sync(0xffffffffu, s2, o);
    }
    __shared__ float sh[16];
    int w = threadIdx.x >> 5, lane = threadIdx.x & 31;
    if (lane == 0) { sh[w] = s; sh[w + 8] = s2; }
    __syncthreads();
    if (threadIdx.x < 32) {
        float a = (threadIdx.x < 8) ? sh[threadIdx.x] : 0.0f;
        float c = (threadIdx.x < 8) ? sh[threadIdx.x + 8] : 0.0f;
#pragma unroll
        for (int o = 16; o; o >>= 1) {
            a += __shfl_xor_sync(0xffffffffu, a, o);
            c += __shfl_xor_sync(0xffffffffu, c, o);
        }
        if (threadIdx.x == 0) { sh[0] = a; sh[1] = c; }
    }
    __syncthreads();
    float invD = 1.0f / (float)D;
    float mu   = sh[0] * invD;
    float var  = sh[1] * invD - mu * mu;
    float rstd = rsqrtf(var + EPSF);

    for (int i = threadIdx.x; i < n4; i += 256) {
        float4 v = x4[i], gg = g4[i], bb = b4[i];
        v.x = (v.x - mu) * rstd * gg.x + bb.x;
        v.y = (v.y - mu) * rstd * gg.y + bb.y;
        v.z = (v.z - mu) * rstd * gg.z + bb.z;
        v.w = (v.w - mu) * rstd * gg.w + bb.w;
        y4[i] = v;
    }
}

// ---------------- softmax over rows of length TKV=256: warp per row ----------------
__global__ __launch_bounds__(256)
void softmax_kernel(float* __restrict__ S, long nrows)
{
    long gw = ((long)blockIdx.x * blockDim.x + threadIdx.x) >> 5;
    if (gw >= nrows) return;
    int lane = threadIdx.x & 31;
    float4* row = (float4*)(S + gw * (long)TKV);
    float4 a = row[lane];
    float4 c = row[lane + 32];

    float m = fmaxf(fmaxf(fmaxf(a.x, a.y), fmaxf(a.z, a.w)),
                    fmaxf(fmaxf(c.x, c.y), fmaxf(c.z, c.w)));
#pragma unroll
    for (int o = 16; o; o >>= 1) m = fmaxf(m, __shfl_xor_sync(0xffffffffu, m, o));

    a.x = __expf(a.x - m); a.y = __expf(a.y - m);
    a.z = __expf(a.z - m); a.w = __expf(a.w - m);
    c.x = __expf(c.x - m); c.y = __expf(c.y - m);
    c.z = __expf(c.z - m); c.w = __expf(c.w - m);

    float s = a.x + a.y + a.z + a.w + c.x + c.y + c.z + c.w;
#pragma unroll
    for (int o = 16; o; o >>= 1) s += __shfl_xor_sync(0xffffffffu, s, o);
    float inv = 1.0f / s;

    a.x *= inv; a.y *= inv; a.z *= inv; a.w *= inv;
    c.x *= inv; c.y *= inv; c.z *= inv; c.w *= inv;
    row[lane] = a;
    row[lane + 32] = c;
}

// ---------------- launch ----------------
extern "C" void kernel_launch(void* const* d_in, const int* in_sizes, int n_in,
                              void* d_out, int out_size)
{
    const float* grid      = (const float*)d_in[0];
    const float* query_pos = (const float*)d_in[1];
    const float* Wq        = (const float*)d_in[2];
    const float* Wk        = (const float*)d_in[3];
    const float* Wv        = (const float*)d_in[4];
    const float* Wo        = (const float*)d_in[5];
    const float* lng_g     = (const float*)d_in[6];
    const float* lng_b     = (const float*)d_in[7];
    const float* lnq_g     = (const float*)d_in[8];
    const float* lnq_b     = (const float*)d_in[9];
    const float* lnm_g     = (const float*)d_in[10];
    const float* lnm_b     = (const float*)d_in[11];
    const float* W1        = (const float*)d_in[12];
    const float* b1        = (const float*)d_in[13];
    const float* W2        = (const float*)d_in[14];
    const float* b2        = (const float*)d_in[15];
    float* out = (float*)d_out;

    float *Kp, *Kn, *V, *qn, *Q, *S, *attn, *x, *xn, *hb;
    cudaGetSymbolAddress((void**)&Kp,   g_Kpre);
    cudaGetSymbolAddress((void**)&Kn,   g_Kn);
    cudaGetSymbolAddress((void**)&V,    g_V);
    cudaGetSymbolAddress((void**)&qn,   g_qn);
    cudaGetSymbolAddress((void**)&Q,    g_Q);
    cudaGetSymbolAddress((void**)&S,    g_S);
    cudaGetSymbolAddress((void**)&attn, g_attn);
    cudaGetSymbolAddress((void**)&x,    g_x);
    cudaGetSymbolAddress((void**)&xn,   g_xn);
    cudaGetSymbolAddress((void**)&hb,   g_h);

    dim3 blk(256);
    const int MG = BB * TKV;       // 4096 grid tokens
    const int MQ = BB * LQ;        // 16384 query tokens

    // 1) Kpre = grid_flat @ Wk ; V = grid_flat @ Wv   (M=4096, K=1024, N=1024)
    gemm_kernel<EPI_NONE, false><<<dim3(SEQ_D / 64, MG / 128, 1), blk>>>(
        grid, Wk, nullptr, nullptr, Kp, MG, SEQ_D, GRID_D,
        GRID_D, SEQ_D, SEQ_D, 0, 0, 0, 0, 0, 0, 1, 1.0f);
    gemm_kernel<EPI_NONE, false><<<dim3(SEQ_D / 64, MG / 128, 1), blk>>>(
        grid, Wv, nullptr, nullptr, V, MG, SEQ_D, GRID_D,
        GRID_D, SEQ_D, SEQ_D, 0, 0, 0, 0, 0, 0, 1, 1.0f);

    // 2) K = LN(Kpre) ; qn = LN(query_pos)
    ln_kernel<<<MG, 256>>>(Kp, lng_g, lng_b, Kn, SEQ_D);
    ln_kernel<<<MQ, 256>>>(query_pos, lnq_g, lnq_b, qn, POS_D);

    // 3) Q = qn @ Wq   (M=16384, K=512, N=1024)
    gemm_kernel<EPI_NONE, false><<<dim3(SEQ_D / 64, MQ / 128, 1), blk>>>(
        qn, Wq, nullptr, nullptr, Q, MQ, SEQ_D, POS_D,
        POS_D, SEQ_D, SEQ_D, 0, 0, 0, 0, 0, 0, 1, 1.0f);

    // 4) scores = (Qh @ Kh^T) * 1/sqrt(64), batched over (b,h)  [NT GEMM]
    gemm_kernel<EPI_NONE, true><<<dim3(TKV / 64, LQ / 128, BB * NH), blk>>>(
        Q, Kn, nullptr, nullptr, S, LQ, TKV, HEAD,
        SEQ_D, SEQ_D, TKV,
        (long)LQ * SEQ_D, (long)HEAD,          // A (Q) strides per b,h
        (long)TKV * SEQ_D, (long)HEAD,         // B (K) strides per b,h
        (long)NH * LQ * TKV, (long)LQ * TKV,   // C (S) strides per b,h
        NH, 0.125f);

    // 5) softmax over last dim (256)
    softmax_kernel<<<(BB * NH * LQ) / 8, 256>>>(S, (long)BB * NH * LQ);

    // 6) attn_h = P @ Vh, batched over (b,h)  [NN GEMM], write merged (B,L,SEQ_D)
    gemm_kernel<EPI_NONE, false><<<dim3(1, LQ / 128, BB * NH), blk>>>(
        S, V, nullptr, nullptr, attn, LQ, HEAD, TKV,
        TKV, SEQ_D, SEQ_D,
        (long)NH * LQ * TKV, (long)LQ * TKV,
        (long)TKV * SEQ_D, (long)HEAD,
        (long)LQ * SEQ_D, (long)HEAD,
        NH, 1.0f);

    // 7) x = Q + attn @ Wo
    gemm_kernel<EPI_RESID, false><<<dim3(SEQ_D / 64, MQ / 128, 1), blk>>>(
        attn, Wo, nullptr, Q, x, MQ, SEQ_D, SEQ_D,
        SEQ_D, SEQ_D, SEQ_D, 0, 0, 0, 0, 0, 0, 1, 1.0f);

    // 8) xn = LN(x)
    ln_kernel<<<MQ, 256>>>(x, lnm_g, lnm_b, xn, SEQ_D);

    // 9) h = gelu(xn @ W1 + b1)   (N = 4096)
    gemm_kernel<EPI_GELU_BIAS, false><<<dim3(MULT * SEQ_D / 64, MQ / 128, 1), blk>>>(
        xn, W1, b1, nullptr, hb, MQ, MULT * SEQ_D, SEQ_D,
        SEQ_D, MULT * SEQ_D, MULT * SEQ_D, 0, 0, 0, 0, 0, 0, 1, 1.0f);

    // 10) out = x + h @ W2 + b2   (K = 4096)
    gemm_kernel<EPI_BIAS_RESID, false><<<dim3(SEQ_D / 64, MQ / 128, 1), blk>>>(
        hb, W2, b2, x, out, MQ, SEQ_D, MULT * SEQ_D,
        MULT * SEQ_D, SEQ_D, SEQ_D, 0, 0, 0, 0, 0, 0, 1, 1.0f);
}

// round 3
// speedup vs baseline: 2.5397x; 2.5397x over previous
#include <cuda_runtime.h>
#include <math.h>
#include <stdint.h>

// Problem constants
#define BB      16
#define GRID_D  1024
#define SEQ_D   1024
#define POS_D   512
#define NH      16
#define HEAD    64
#define LQ      1024
#define TKV     256
#define MULT    4
#define EPSF    1e-5f

// ---------------- scratch (static device memory) ---------------
__device__ float g_Kpre[(size_t)BB * TKV * SEQ_D];
__device__ float g_Kn  [(size_t)BB * TKV * SEQ_D];
__device__ float g_V   [(size_t)BB * TKV * SEQ_D];
__device__ float g_qn  [(size_t)BB * LQ * POS_D];
__device__ float g_Q   [(size_t)BB * LQ * SEQ_D];
__device__ float g_S   [(size_t)BB * NH * LQ * TKV];
__device__ float g_attn[(size_t)BB * LQ * SEQ_D];
__device__ float g_x   [(size_t)BB * LQ * SEQ_D];
__device__ float g_xn  [(size_t)BB * LQ * SEQ_D];
__device__ float g_h   [(size_t)BB * LQ * MULT * SEQ_D];

// ---------------- helpers ----------------
__device__ __forceinline__ float gelu_f(float v) {
    float v3 = v * v * v;
    return 0.5f * v * (1.0f + tanhf(0.7978845608028654f * (v + 0.044715f * v3)));
}

__device__ __forceinline__ float f2tf32(float x) {
    uint32_t u;
    asm("cvt.rna.tf32.f32 %0, %1;" : "=r"(u) : "f"(x));
    return __uint_as_float(u);
}

enum { EPI_NONE = 0, EPI_RESID = 1, EPI_GELU_BIAS = 2, EPI_BIAS_RESID = 3 };

// =================================================================
// tf32 tensor-core GEMM: C[M,N] = A[M,K] @ B[K,N] (+ epilogue)
// BM=128, BN=128, BK=16; 256 threads = 8 warps (4 m-rows x 2 n-cols),
// each warp 32x64 via m16n8k8. Requires M%128==0, N%128==0, K%16==0.
// =================================================================
template <int EPI>
__global__ __launch_bounds__(256, 2)
void gemm_tf32(const float* __restrict__ A, const float* __restrict__ Bm,
               const float* __restrict__ bias, const float* __restrict__ res,
               float* __restrict__ C, int M, int N, int K, float alpha)
{
    constexpr int BM = 128, BN = 128, BK = 16;
    constexpr int ASTR = BK + 4;   // 20 floats per A row (16B-aligned rows)
    constexpr int BSTR = BN + 8;   // 136 floats per B row

    __shared__ float As[2][BM][ASTR];
    __shared__ float Bs[2][BK][BSTR];

    const int tid  = threadIdx.x;
    const int lane = tid & 31;
    const int warp = tid >> 5;
    const int wm   = warp >> 1;    // 0..3
    const int wn   = warp & 1;     // 0..1
    const int m0   = blockIdx.y * BM;
    const int n0   = blockIdx.x * BN;

    // staging indices
    const int amr[2] = { (tid + 0)   >> 2, (tid + 256) >> 2 };   // 0..127
    const int akc    = tid & 3;
    const int bkr[2] = { (tid + 0)   >> 5, (tid + 256) >> 5 };   // 0..15
    const int bnc    = tid & 31;

    float acc[2][8][4];
#pragma unroll
    for (int mt = 0; mt < 2; mt++)
#pragma unroll
        for (int nt = 0; nt < 8; nt++)
#pragma unroll
            for (int j = 0; j < 4; j++) acc[mt][nt][j] = 0.0f;

    float4 ra[2], rb[2];
    auto ldg = [&](int k0) {
#pragma unroll
        for (int i = 0; i < 2; i++) {
            ra[i] = *(const float4*)(A + (size_t)(m0 + amr[i]) * K + k0 + akc * 4);
            rb[i] = *(const float4*)(Bm + (size_t)(k0 + bkr[i]) * N + n0 + bnc * 4);
        }
    };
    auto sts = [&](int buf) {
#pragma unroll
        for (int i = 0; i < 2; i++) {
            float4 va = make_float4(f2tf32(ra[i].x), f2tf32(ra[i].y),
                                    f2tf32(ra[i].z), f2tf32(ra[i].w));
            float4 vb = make_float4(f2tf32(rb[i].x), f2tf32(rb[i].y),
                                    f2tf32(rb[i].z), f2tf32(rb[i].w));
            *(float4*)&As[buf][amr[i]][akc * 4] = va;
            *(float4*)&Bs[buf][bkr[i]][bnc * 4] = vb;
        }
    };

    const int nIter = K / BK;
    ldg(0);
    sts(0);
    __syncthreads();

    const int g4 = lane >> 2;   // 0..7
    const int t4 = lane & 3;    // 0..3

    for (int it = 0; it < nIter; ++it) {
        int cur = it & 1;
        if (it + 1 < nIter) ldg((it + 1) * BK);

#pragma unroll
        for (int ks = 0; ks < 2; ks++) {
            uint32_t af[2][4], bf[8][2];
#pragma unroll
            for (int mt = 0; mt < 2; mt++) {
                int r = wm * 32 + mt * 16 + g4;
                int kk = ks * 8 + t4;
                af[mt][0] = __float_as_uint(As[cur][r][kk]);
                af[mt][1] = __float_as_uint(As[cur][r + 8][kk]);
                af[mt][2] = __float_as_uint(As[cur][r][kk + 4]);
                af[mt][3] = __float_as_uint(As[cur][r + 8][kk + 4]);
            }
#pragma unroll
            for (int nt = 0; nt < 8; nt++) {
                int nn = wn * 64 + nt * 8 + g4;
                int kk = ks * 8 + t4;
                bf[nt][0] = __float_as_uint(Bs[cur][kk][nn]);
                bf[nt][1] = __float_as_uint(Bs[cur][kk + 4][nn]);
            }
#pragma unroll
            for (int mt = 0; mt < 2; mt++)
#pragma unroll
                for (int nt = 0; nt < 8; nt++) {
                    asm volatile(
                        "mma.sync.aligned.m16n8k8.row.col.f32.tf32.tf32.f32 "
                        "{%0,%1,%2,%3}, {%4,%5,%6,%7}, {%8,%9}, {%0,%1,%2,%3};"
                        : "+f"(acc[mt][nt][0]), "+f"(acc[mt][nt][1]),
                          "+f"(acc[mt][nt][2]), "+f"(acc[mt][nt][3])
                        : "r"(af[mt][0]), "r"(af[mt][1]), "r"(af[mt][2]), "r"(af[mt][3]),
                          "r"(bf[nt][0]), "r"(bf[nt][1]));
                }
        }

        if (it + 1 < nIter) sts(cur ^ 1);
        __syncthreads();
    }

    // Epilogue: each (mt,nt) fragment -> rows r, r+8; cols c, c+1
#pragma unroll
    for (int mt = 0; mt < 2; mt++) {
#pragma unroll
        for (int nt = 0; nt < 8; nt++) {
            int r = m0 + wm * 32 + mt * 16 + g4;
            int c = n0 + wn * 64 + nt * 8 + 2 * t4;
#pragma unroll
            for (int half = 0; half < 2; half++) {
                int rr = r + half * 8;
                float2 v = make_float2(acc[mt][nt][half * 2 + 0] * alpha,
                                       acc[mt][nt][half * 2 + 1] * alpha);
                if (EPI == EPI_GELU_BIAS) {
                    float2 bv = *(const float2*)(bias + c);
                    v.x = gelu_f(v.x + bv.x);
                    v.y = gelu_f(v.y + bv.y);
                } else if (EPI == EPI_RESID) {
                    float2 rv = *(const float2*)(res + (size_t)rr * N + c);
                    v.x += rv.x; v.y += rv.y;
                } else if (EPI == EPI_BIAS_RESID) {
                    float2 bv = *(const float2*)(bias + c);
                    float2 rv = *(const float2*)(res + (size_t)rr * N + c);
                    v.x += bv.x + rv.x; v.y += bv.y + rv.y;
                }
                *(float2*)(C + (size_t)rr * N + c) = v;
            }
        }
    }
}

// =================================================================
// fp32 SIMT GEMM (attention score / PV batched GEMMs)
// =================================================================
template <int EPI, bool TRB>
__global__ __launch_bounds__(256)
void gemm_kernel(const float* __restrict__ A, const float* __restrict__ Bm,
                 const float* __restrict__ bias, const float* __restrict__ res,
                 float* __restrict__ C,
                 int M, int N, int K, int lda, int ldb, int ldc,
                 long sAb, long sAh, long sBb, long sBh, long sCb, long sCh,
                 int nh, float alpha)
{
    constexpr int BM = 128, BN = 64, BK = 16;
    __shared__ float As[BK][BM];
    __shared__ float Bs[BK][BN];

    int z  = blockIdx.z;
    int zb = z / nh, zh = z % nh;
    A  += (size_t)zb * sAb + (size_t)zh * sAh;
    Bm += (size_t)zb * sBb + (size_t)zh * sBh;
    C  += (size_t)zb * sCb + (size_t)zh * sCh;
    if (EPI == EPI_RESID || EPI == EPI_BIAS_RESID)
        res += (size_t)zb * sCb + (size_t)zh * sCh;

    int tid = threadIdx.x;
    int tx = tid & 15, ty = tid >> 4;
    int m0 = blockIdx.y * BM, n0 = blockIdx.x * BN;

    float acc[8][4];
#pragma unroll
    for (int i = 0; i < 8; i++)
#pragma unroll
        for (int j = 0; j < 4; j++) acc[i][j] = 0.0f;

    for (int k0 = 0; k0 < K; k0 += BK) {
#pragma unroll
        for (int i = 0; i < 2; i++) {
            int idx = tid + i * 256;
            int r   = idx >> 2;
            int c4  = (idx & 3) << 2;
            float4 v = *(const float4*)(A + (size_t)(m0 + r) * lda + k0 + c4);
            As[c4 + 0][r] = v.x; As[c4 + 1][r] = v.y;
            As[c4 + 2][r] = v.z; As[c4 + 3][r] = v.w;
        }
        if (!TRB) {
            int r  = tid >> 4;
            int c4 = (tid & 15) << 2;
            float4 v = *(const float4*)(Bm + (size_t)(k0 + r) * ldb + n0 + c4);
            *(float4*)&Bs[r][c4] = v;
        } else {
            int r  = tid >> 2;
            int c4 = (tid & 3) << 2;
            float4 v = *(const float4*)(Bm + (size_t)(n0 + r) * ldb + k0 + c4);
            Bs[c4 + 0][r] = v.x; Bs[c4 + 1][r] = v.y;
            Bs[c4 + 2][r] = v.z; Bs[c4 + 3][r] = v.w;
        }
        __syncthreads();

#pragma unroll
        for (int k = 0; k < BK; k++) {
            float a[8], bf[4];
            *(float4*)&a[0] = *(const float4*)&As[k][ty * 8];
            *(float4*)&a[4] = *(const float4*)&As[k][ty * 8 + 4];
            *(float4*)&bf[0] = *(const float4*)&Bs[k][tx * 4];
#pragma unroll
            for (int i = 0; i < 8; i++)
#pragma unroll
                for (int j = 0; j < 4; j++)
                    acc[i][j] = fmaf(a[i], bf[j], acc[i][j]);
        }
        __syncthreads();
    }

    int c = n0 + tx * 4;
#pragma unroll
    for (int i = 0; i < 8; i++) {
        int r = m0 + ty * 8 + i;
        float4 v = make_float4(acc[i][0] * alpha, acc[i][1] * alpha,
                               acc[i][2] * alpha, acc[i][3] * alpha);
        if (EPI == EPI_GELU_BIAS) {
            float4 bv = *(const float4*)(bias + c);
            v.x = gelu_f(v.x + bv.x); v.y = gelu_f(v.y + bv.y);
            v.z = gelu_f(v.z + bv.z); v.w = gelu_f(v.w + bv.w);
        } else if (EPI == EPI_RESID) {
            float4 rv = *(const float4*)(res + (size_t)r * ldc + c);
            v.x += rv.x; v.y += rv.y; v.z += rv.z; v.w += rv.w;
        } else if (EPI == EPI_BIAS_RESID) {
            float4 bv = *(const float4*)(bias + c);
            float4 rv = *(const float4*)(res + (size_t)r * ldc + c);
            v.x += bv.x + rv.x; v.y += bv.y + rv.y;
            v.z += bv.z + rv.z; v.w += bv.w + rv.w;
        }
        *(float4*)(C + (size_t)r * ldc + c) = v;
    }
}

// ---------------- LayerNorm ----------------
__global__ __launch_bounds__(256)
void ln_kernel(const float* __restrict__ X, const float* __restrict__ g,
               const float* __restrict__ b, float* __restrict__ Y, int D)
{
    long row = blockIdx.x;
    const float4* x4 = (const float4*)(X + row * (long)D);
    float4*       y4 = (float4*)(Y + row * (long)D);
    const float4* g4 = (const float4*)g;
    const float4* b4 = (const float4*)b;
    int n4 = D >> 2;

    float s = 0.0f, s2 = 0.0f;
    for (int i = threadIdx.x; i < n4; i += 256) {
        float4 v = x4[i];
        s  += v.x + v.y + v.z + v.w;
        s2 += v.x * v.x + v.y * v.y + v.z * v.z + v.w * v.w;
    }
#pragma unroll
    for (int o = 16; o; o >>= 1) {
        s  += __shfl_xor_sync(0xffffffffu, s, o);
        s2 += __shfl_xor_sync(0xffffffffu, s2, o);
    }
    __shared__ float sh[16];
    int w = threadIdx.x >> 5, lane = threadIdx.x & 31;
    if (lane == 0) { sh[w] = s; sh[w + 8] = s2; }
    __syncthreads();
    if (threadIdx.x < 32) {
        float a = (threadIdx.x < 8) ? sh[threadIdx.x] : 0.0f;
        float c = (threadIdx.x < 8) ? sh[threadIdx.x + 8] : 0.0f;
#pragma unroll
        for (int o = 16; o; o >>= 1) {
            a += __shfl_xor_sync(0xffffffffu, a, o);
            c += __shfl_xor_sync(0xffffffffu, c, o);
        }
        if (threadIdx.x == 0) { sh[0] = a; sh[1] = c; }
    }
    __syncthreads();
    float invD = 1.0f / (float)D;
    float mu   = sh[0] * invD;
    float var  = sh[1] * invD - mu * mu;
    float rstd = rsqrtf(var + EPSF);

    for (int i = threadIdx.x; i < n4; i += 256) {
        float4 v = x4[i], gg = g4[i], bb = b4[i];
        v.x = (v.x - mu) * rstd * gg.x + bb.x;
        v.y = (v.y - mu) * rstd * gg.y + bb.y;
        v.z = (v.z - mu) * rstd * gg.z + bb.z;
        v.w = (v.w - mu) * rstd * gg.w + bb.w;
        y4[i] = v;
    }
}

// ---------------- softmax (rows of 256, warp per row) ----------------
__global__ __launch_bounds__(256)
void softmax_kernel(float* __restrict__ S, long nrows)
{
    long gw = ((long)blockIdx.x * blockDim.x + threadIdx.x) >> 5;
    if (gw >= nrows) return;
    int lane = threadIdx.x & 31;
    float4* row = (float4*)(S + gw * (long)TKV);
    float4 a = row[lane];
    float4 c = row[lane + 32];

    float m = fmaxf(fmaxf(fmaxf(a.x, a.y), fmaxf(a.z, a.w)),
                    fmaxf(fmaxf(c.x, c.y), fmaxf(c.z, c.w)));
#pragma unroll
    for (int o = 16; o; o >>= 1) m = fmaxf(m, __shfl_xor_sync(0xffffffffu, m, o));

    a.x = __expf(a.x - m); a.y = __expf(a.y - m);
    a.z = __expf(a.z - m); a.w = __expf(a.w - m);
    c.x = __expf(c.x - m); c.y = __expf(c.y - m);
    c.z = __expf(c.z - m); c.w = __expf(c.w - m);

    float s = a.x + a.y + a.z + a.w + c.x + c.y + c.z + c.w;
#pragma unroll
    for (int o = 16; o; o >>= 1) s += __shfl_xor_sync(0xffffffffu, s, o);
    float inv = 1.0f / s;

    a.x *= inv; a.y *= inv; a.z *= inv; a.w *= inv;
    c.x *= inv; c.y *= inv; c.z *= inv; c.w *= inv;
    row[lane] = a;
    row[lane + 32] = c;
}

// ---------------- launch ----------------
extern "C" void kernel_launch(void* const* d_in, const int* in_sizes, int n_in,
                              void* d_out, int out_size)
{
    const float* grid      = (const float*)d_in[0];
    const float* query_pos = (const float*)d_in[1];
    const float* Wq        = (const float*)d_in[2];
    const float* Wk        = (const float*)d_in[3];
    const float* Wv        = (const float*)d_in[4];
    const float* Wo        = (const float*)d_in[5];
    const float* lng_g     = (const float*)d_in[6];
    const float* lng_b     = (const float*)d_in[7];
    const float* lnq_g     = (const float*)d_in[8];
    const float* lnq_b     = (const float*)d_in[9];
    const float* lnm_g     = (const float*)d_in[10];
    const float* lnm_b     = (const float*)d_in[11];
    const float* W1        = (const float*)d_in[12];
    const float* b1        = (const float*)d_in[13];
    const float* W2        = (const float*)d_in[14];
    const float* b2        = (const float*)d_in[15];
    float* out = (float*)d_out;

    float *Kp, *Kn, *V, *qn, *Q, *S, *attn, *x, *xn, *hb;
    cudaGetSymbolAddress((void**)&Kp,   g_Kpre);
    cudaGetSymbolAddress((void**)&Kn,   g_Kn);
    cudaGetSymbolAddress((void**)&V,    g_V);
    cudaGetSymbolAddress((void**)&qn,   g_qn);
    cudaGetSymbolAddress((void**)&Q,    g_Q);
    cudaGetSymbolAddress((void**)&S,    g_S);
    cudaGetSymbolAddress((void**)&attn, g_attn);
    cudaGetSymbolAddress((void**)&x,    g_x);
    cudaGetSymbolAddress((void**)&xn,   g_xn);
    cudaGetSymbolAddress((void**)&hb,   g_h);

    dim3 blk(256);
    const int MG = BB * TKV;       // 4096
    const int MQ = BB * LQ;        // 16384

    // 1) Kpre = grid @ Wk ; V = grid @ Wv
    gemm_tf32<EPI_NONE><<<dim3(SEQ_D / 128, MG / 128), blk>>>(
        grid, Wk, nullptr, nullptr, Kp, MG, SEQ_D, GRID_D, 1.0f);
    gemm_tf32<EPI_NONE><<<dim3(SEQ_D / 128, MG / 128), blk>>>(
        grid, Wv, nullptr, nullptr, V, MG, SEQ_D, GRID_D, 1.0f);

    // 2) K = LN(Kpre) ; qn = LN(query_pos)
    ln_kernel<<<MG, 256>>>(Kp, lng_g, lng_b, Kn, SEQ_D);
    ln_kernel<<<MQ, 256>>>(query_pos, lnq_g, lnq_b, qn, POS_D);

    // 3) Q = qn @ Wq
    gemm_tf32<EPI_NONE><<<dim3(SEQ_D / 128, MQ / 128), blk>>>(
        qn, Wq, nullptr, nullptr, Q, MQ, SEQ_D, POS_D, 1.0f);

    // 4) scores = (Qh @ Kh^T) * 1/8, batched over (b,h) [fp32 NT]
    gemm_kernel<EPI_NONE, true><<<dim3(TKV / 64, LQ / 128, BB * NH), blk>>>(
        Q, Kn, nullptr, nullptr, S, LQ, TKV, HEAD,
        SEQ_D, SEQ_D, TKV,
        (long)LQ * SEQ_D, (long)HEAD,
        (long)TKV * SEQ_D, (long)HEAD,
        (long)NH * LQ * TKV, (long)LQ * TKV,
        NH, 0.125f);

    // 5) softmax
    softmax_kernel<<<(BB * NH * LQ) / 8, 256>>>(S, (long)BB * NH * LQ);

    // 6) attn = P @ Vh [fp32 NN, batched]
    gemm_kernel<EPI_NONE, false><<<dim3(1, LQ / 128, BB * NH), blk>>>(
        S, V, nullptr, nullptr, attn, LQ, HEAD, TKV,
        TKV, SEQ_D, SEQ_D,
        (long)NH * LQ * TKV, (long)LQ * TKV,
        (long)TKV * SEQ_D, (long)HEAD,
        (long)LQ * SEQ_D, (long)HEAD,
        NH, 1.0f);

    // 7) x = Q + attn @ Wo
    gemm_tf32<EPI_RESID><<<dim3(SEQ_D / 128, MQ / 128), blk>>>(
        attn, Wo, nullptr, Q, x, MQ, SEQ_D, SEQ_D, 1.0f);

    // 8) xn = LN(x)
    ln_kernel<<<MQ, 256>>>(x, lnm_g, lnm_b, xn, SEQ_D);

    // 9) h = gelu(xn @ W1 + b1)
    gemm_tf32<EPI_GELU_BIAS><<<dim3(MULT * SEQ_D / 128, MQ / 128), blk>>>(
        xn, W1, b1, nullptr, hb, MQ, MULT * SEQ_D, SEQ_D, 1.0f);

    // 10) out = x + h @ W2 + b2
    gemm_tf32<EPI_BIAS_RESID><<<dim3(SEQ_D / 128, MQ / 128), blk>>>(
        hb, W2, b2, x, out, MQ, SEQ_D, MULT * SEQ_D, 1.0f);
}

// round 5
// speedup vs baseline: 4.3165x; 1.6996x over previous
#include <cuda_runtime.h>
#include <cuda_fp16.h>
#include <math.h>
#include <stdint.h>

// Problem constants
#define BB      16
#define GRID_D  1024
#define SEQ_D   1024
#define POS_D   512
#define NH      16
#define HEAD    64
#define LQ      1024
#define TKV     256
#define MULT    4
#define EPSF    1e-5f

// ---------------- scratch (static device memory) ---------------
__device__ float  g_Kpre[(size_t)BB * TKV * SEQ_D];
__device__ float  g_Kn  [(size_t)BB * TKV * SEQ_D];
__device__ float  g_V   [(size_t)BB * TKV * SEQ_D];
__device__ float  g_qn  [(size_t)BB * LQ * POS_D];
__device__ float  g_Q   [(size_t)BB * LQ * SEQ_D];
__device__ float  g_S   [(size_t)BB * NH * LQ * TKV];
__device__ float  g_attn[(size_t)BB * LQ * SEQ_D];
__device__ float  g_x   [(size_t)BB * LQ * SEQ_D];
__device__ float  g_xn  [(size_t)BB * LQ * SEQ_D];
__device__ __half g_h   [(size_t)BB * LQ * MULT * SEQ_D];     // fp16 intermediate
// transposed fp16 weights [N][K]
__device__ __half g_WkT [(size_t)SEQ_D * GRID_D];
__device__ __half g_WvT [(size_t)SEQ_D * GRID_D];
__device__ __half g_WqT [(size_t)SEQ_D * POS_D];
__device__ __half g_WoT [(size_t)SEQ_D * SEQ_D];
__device__ __half g_W1T [(size_t)MULT * SEQ_D * SEQ_D];
__device__ __half g_W2T [(size_t)SEQ_D * MULT * SEQ_D];
// V transposed per head: VT[b*NH+h][d=64][t=256], fp16
__device__ __half g_VT  [(size_t)BB * NH * HEAD * TKV];

// ---------------- helpers ----------------
__device__ __forceinline__ float gelu_f(float v) {
    float v3 = v * v * v;
    return 0.5f * v * (1.0f + tanhf(0.7978845608028654f * (v + 0.044715f * v3)));
}
__device__ __forceinline__ uint32_t sptr(const void* p) {
    uint32_t a;
    asm("{ .reg .u64 t; cvta.to.shared.u64 t, %1; cvt.u32.u64 %0, t; }" : "=r"(a) : "l"(p));
    return a;
}
__device__ __forceinline__ uint32_t pack2(float a, float b) {
    __half2 h = __float22half2_rn(make_float2(a, b));
    return *reinterpret_cast<uint32_t*>(&h);
}

#define LDMX4(r0, r1, r2, r3, addr) \
    asm volatile("ldmatrix.sync.aligned.m8n8.x4.shared.b16 {%0,%1,%2,%3}, [%4];" \
                 : "=r"(r0), "=r"(r1), "=r"(r2), "=r"(r3) : "r"(addr))

#define MMA16816(d, a, b) \
    asm volatile("mma.sync.aligned.m16n8k16.row.col.f32.f16.f16.f32 " \
                 "{%0,%1,%2,%3}, {%4,%5,%6,%7}, {%8,%9}, {%0,%1,%2,%3};" \
                 : "+f"((d)[0]), "+f"((d)[1]), "+f"((d)[2]), "+f"((d)[3]) \
                 : "r"((a)[0]), "r"((a)[1]), "r"((a)[2]), "r"((a)[3]), \
                   "r"((b)[0]), "r"((b)[1]))

enum { EPI_NONE = 0, EPI_RESID = 1, EPI_GELU_BIAS = 2, EPI_BIAS_RESID = 3 };

// =================================================================
// fp16 tensor-core GEMM (NT): C[M,N] = alpha * A[M,K] @ BT[N,K]^T (+epi)
// BM=128, BN in {64,128}, BK=32, 256 threads = 8 warps (4m x 2n).
// A,BT element types TA/TB in {float,__half}; staged to fp16 smem; fp32 accum.
// Batched over blockIdx.z with (b,h) split strides (elements of own type).
// =================================================================
template <typename TA, typename TB, typename TC, int EPI, int BN>
__global__ __launch_bounds__(256)
void gemm_h(const TA* __restrict__ A, const TB* __restrict__ BT,
            const float* __restrict__ bias, const float* __restrict__ res,
            TC* __restrict__ C,
            int M, int N, int K, int lda, int ldb, int ldc,
            long sAb, long sAh, long sBb, long sBh, long sCb, long sCh,
            int nh, float alpha)
{
    constexpr int BM = 128, BK = 32;
    constexpr int STR = 40;              // halves per smem row (80B; conflict-benign)
    constexpr int WN = BN / 2;           // per-warp n extent
    constexpr int NT = BN / 16;          // n8 tiles per warp (8 or 4)
    constexpr int NSA = (BM * 4) / 256;  // A 16B segments per thread (2)
    constexpr int NSB = (BN * 4) / 256;  // B segments per thread (2 or 1)

    __shared__ __half As[2][BM][STR];
    __shared__ __half Bs[2][BN][STR];

    const int tid  = threadIdx.x;
    const int lane = tid & 31;
    const int warp = tid >> 5;
    const int wm   = warp >> 1;
    const int wn   = warp & 1;
    const int m0   = blockIdx.y * BM;
    const int n0   = blockIdx.x * BN;

    const int z  = blockIdx.z;
    const int zb = z / nh, zh = z % nh;
    const TA* Ab = A  + (size_t)zb * sAb + (size_t)zh * sAh;
    const TB* Bb = BT + (size_t)zb * sBb + (size_t)zh * sBh;
    TC*       Cb = C  + (size_t)zb * sCb + (size_t)zh * sCh;
    const float* rb = res;
    if (EPI == EPI_RESID || EPI == EPI_BIAS_RESID)
        rb = res + (size_t)zb * sCb + (size_t)zh * sCh;

    float acc[2][NT][4];
#pragma unroll
    for (int mt = 0; mt < 2; mt++)
#pragma unroll
        for (int nt = 0; nt < NT; nt++)
#pragma unroll
            for (int j = 0; j < 4; j++) acc[mt][nt][j] = 0.0f;

    // raw staging registers
    float4 raF[NSA][2]; uint4 raH[NSA];
    float4 rbF[NSB][2]; uint4 rbH[NSB];

    auto ldgA = [&](int k0) {
#pragma unroll
        for (int i = 0; i < NSA; i++) {
            int s = tid + i * 256, r = s >> 2, cs = s & 3;
            if (sizeof(TA) == 4) {
                const float* p = (const float*)(const void*)Ab
                               + (size_t)(m0 + r) * lda + k0 + cs * 8;
                raF[i][0] = *(const float4*)p;
                raF[i][1] = *(const float4*)(p + 4);
            } else {
                const __half* p = (const __half*)(const void*)Ab
                                + (size_t)(m0 + r) * lda + k0 + cs * 8;
                raH[i] = *(const uint4*)p;
            }
        }
    };
    auto ldgB = [&](int k0) {
#pragma unroll
        for (int i = 0; i < NSB; i++) {
            int s = tid + i * 256, r = s >> 2, cs = s & 3;
            if (sizeof(TB) == 4) {
                const float* p = (const float*)(const void*)Bb
                               + (size_t)(n0 + r) * ldb + k0 + cs * 8;
                rbF[i][0] = *(const float4*)p;
                rbF[i][1] = *(const float4*)(p + 4);
            } else {
                const __half* p = (const __half*)(const void*)Bb
                                + (size_t)(n0 + r) * ldb + k0 + cs * 8;
                rbH[i] = *(const uint4*)p;
            }
        }
    };
    auto stsA = [&](int buf) {
#pragma unroll
        for (int i = 0; i < NSA; i++) {
            int s = tid + i * 256, r = s >> 2, cs = s & 3;
            uint4 u;
            if (sizeof(TA) == 4) {
                u.x = pack2(raF[i][0].x, raF[i][0].y);
                u.y = pack2(raF[i][0].z, raF[i][0].w);
                u.z = pack2(raF[i][1].x, raF[i][1].y);
                u.w = pack2(raF[i][1].z, raF[i][1].w);
            } else u = raH[i];
            *(uint4*)&As[buf][r][cs * 8] = u;
        }
    };
    auto stsB = [&](int buf) {
#pragma unroll
        for (int i = 0; i < NSB; i++) {
            int s = tid + i * 256, r = s >> 2, cs = s & 3;
            uint4 u;
            if (sizeof(TB) == 4) {
                u.x = pack2(rbF[i][0].x, rbF[i][0].y);
                u.y = pack2(rbF[i][0].z, rbF[i][0].w);
                u.z = pack2(rbF[i][1].x, rbF[i][1].y);
                u.w = pack2(rbF[i][1].z, rbF[i][1].w);
            } else u = rbH[i];
            *(uint4*)&Bs[buf][r][cs * 8] = u;
        }
    };

    const int lr = lane & 15;        // ldmatrix row select
    const int lc = lane >> 4;        // ldmatrix col half select

    auto compute = [&](int buf) {
#pragma unroll
        for (int ks = 0; ks < 2; ks++) {
            uint32_t af[2][4];
#pragma unroll
            for (int mt = 0; mt < 2; mt++) {
                uint32_t ad = sptr(&As[buf][wm * 32 + mt * 16 + lr][ks * 16 + lc * 8]);
                LDMX4(af[mt][0], af[mt][1], af[mt][2], af[mt][3], ad);
            }
            uint32_t bf[NT][2];
#pragma unroll
            for (int np = 0; np < NT / 2; np++) {
                uint32_t r0, r1, r2, r3;
                uint32_t bd = sptr(&Bs[buf][wn * WN + np * 16 + lr][ks * 16 + lc * 8]);
                LDMX4(r0, r1, r2, r3, bd);
                bf[np * 2 + 0][0] = r0; bf[np * 2 + 0][1] = r2;
                bf[np * 2 + 1][0] = r1; bf[np * 2 + 1][1] = r3;
            }
#pragma unroll
            for (int mt = 0; mt < 2; mt++)
#pragma unroll
                for (int nt = 0; nt < NT; nt++)
                    MMA16816(acc[mt][nt], af[mt], bf[nt]);
        }
    };

    const int nk = K / BK;
    ldgA(0); ldgB(0); stsA(0); stsB(0);
    __syncthreads();

    for (int it = 0; it < nk; ++it) {
        const int cur = it & 1;
        if (it + 1 < nk) { ldgA((it + 1) * BK); ldgB((it + 1) * BK); }
        compute(cur);
        if (it + 1 < nk) { stsA(cur ^ 1); stsB(cur ^ 1); }
        __syncthreads();
    }

    // epilogue
    const int g4 = lane >> 2, t4 = lane & 3;
#pragma unroll
    for (int mt = 0; mt < 2; mt++) {
#pragma unroll
        for (int nt = 0; nt < NT; nt++) {
            int r = m0 + wm * 32 + mt * 16 + g4;
            int c = n0 + wn * WN + nt * 8 + 2 * t4;
#pragma unroll
            for (int half = 0; half < 2; half++) {
                int rr = r + half * 8;
                float2 v = make_float2(acc[mt][nt][half * 2 + 0] * alpha,
                                       acc[mt][nt][half * 2 + 1] * alpha);
                if (EPI == EPI_GELU_BIAS) {
                    float2 bv = *(const float2*)(bias + c);
                    v.x = gelu_f(v.x + bv.x);
                    v.y = gelu_f(v.y + bv.y);
                } else if (EPI == EPI_RESID) {
                    float2 rv = *(const float2*)(rb + (size_t)rr * ldc + c);
                    v.x += rv.x; v.y += rv.y;
                } else if (EPI == EPI_BIAS_RESID) {
                    float2 bv = *(const float2*)(bias + c);
                    float2 rv = *(const float2*)(rb + (size_t)rr * ldc + c);
                    v.x += bv.x + rv.x; v.y += bv.y + rv.y;
                }
                if (sizeof(TC) == 4) {
                    *(float2*)((float*)(void*)Cb + (size_t)rr * ldc + c) = v;
                } else {
                    __half2 h = __float22half2_rn(v);
                    *(__half2*)((__half*)(void*)Cb + (size_t)rr * ldc + c) = h;
                }
            }
        }
    }
}

// ---------------- weight transpose: WT[n][k] = half(W[k][n]) ----------------
__global__ __launch_bounds__(256)
void transpose_kernel(const float* __restrict__ W, __half* __restrict__ WT,
                      int K, int N)
{
    __shared__ float t[32][33];
    int n0 = blockIdx.x * 32, k0 = blockIdx.y * 32;
    int tx = threadIdx.x & 31, ty = threadIdx.x >> 5;  // 32 x 8
#pragma unroll
    for (int i = 0; i < 32; i += 8)
        t[ty + i][tx] = W[(size_t)(k0 + ty + i) * N + n0 + tx];
    __syncthreads();
#pragma unroll
    for (int i = 0; i < 32; i += 8)
        WT[(size_t)(n0 + ty + i) * K + k0 + tx] = __float2half_rn(t[tx][ty + i]);
}

// ---------------- V transpose per head: VT[bh][d][t] = half(V[b][t][h*64+d]) --
__global__ __launch_bounds__(256)
void vt_kernel(const float* __restrict__ V, __half* __restrict__ VT)
{
    __shared__ float t[32][33];
    int t0 = blockIdx.x * 32;            // token
    int d0 = blockIdx.y * 32;            // head dim block (0 or 32)
    int bh = blockIdx.z;
    int b = bh / NH, h = bh % NH;
    int tx = threadIdx.x & 31, ty = threadIdx.x >> 5;
#pragma unroll
    for (int i = 0; i < 32; i += 8)
        t[ty + i][tx] = V[((size_t)b * TKV + t0 + ty + i) * SEQ_D + h * HEAD + d0 + tx];
    __syncthreads();
#pragma unroll
    for (int i = 0; i < 32; i += 8)
        VT[((size_t)bh * HEAD + d0 + ty + i) * TKV + t0 + tx] =
            __float2half_rn(t[tx][ty + i]);
}

// ---------------- LayerNorm ----------------
__global__ __launch_bounds__(256)
void ln_kernel(const float* __restrict__ X, const float* __restrict__ g,
               const float* __restrict__ b, float* __restrict__ Y, int D)
{
    long row = blockIdx.x;
    const float4* x4 = (const float4*)(X + row * (long)D);
    float4*       y4 = (float4*)(Y + row * (long)D);
    const float4* g4 = (const float4*)g;
    const float4* b4 = (const float4*)b;
    int n4 = D >> 2;

    float s = 0.0f, s2 = 0.0f;
    for (int i = threadIdx.x; i < n4; i += 256) {
        float4 v = x4[i];
        s  += v.x + v.y + v.z + v.w;
        s2 += v.x * v.x + v.y * v.y + v.z * v.z + v.w * v.w;
    }
#pragma unroll
    for (int o = 16; o; o >>= 1) {
        s  += __shfl_xor_sync(0xffffffffu, s, o);
        s2 += __shfl_xor_sync(0xffffffffu, s2, o);
    }
    __shared__ float sh[16];
    int w = threadIdx.x >> 5, lane = threadIdx.x & 31;
    if (lane == 0) { sh[w] = s; sh[w + 8] = s2; }
    __syncthreads();
    if (threadIdx.x < 32) {
        float a = (threadIdx.x < 8) ? sh[threadIdx.x] : 0.0f;
        float c = (threadIdx.x < 8) ? sh[threadIdx.x + 8] : 0.0f;
#pragma unroll
        for (int o = 16; o; o >>= 1) {
            a += __shfl_xor_sync(0xffffffffu, a, o);
            c += __shfl_xor_sync(0xffffffffu, c, o);
        }
        if (threadIdx.x == 0) { sh[0] = a; sh[1] = c; }
    }
    __syncthreads();
    float invD = 1.0f / (float)D;
    float mu   = sh[0] * invD;
    float var  = sh[1] * invD - mu * mu;
    float rstd = rsqrtf(var + EPSF);

    for (int i = threadIdx.x; i < n4; i += 256) {
        float4 v = x4[i], gg = g4[i], bb = b4[i];
        v.x = (v.x - mu) * rstd * gg.x + bb.x;
        v.y = (v.y - mu) * rstd * gg.y + bb.y;
        v.z = (v.z - mu) * rstd * gg.z + bb.z;
        v.w = (v.w - mu) * rstd * gg.w + bb.w;
        y4[i] = v;
    }
}

// ---------------- softmax (rows of 256, warp per row) ----------------
__global__ __launch_bounds__(256)
void softmax_kernel(float* __restrict__ S, long nrows)
{
    long gw = ((long)blockIdx.x * blockDim.x + threadIdx.x) >> 5;
    if (gw >= nrows) return;
    int lane = threadIdx.x & 31;
    float4* row = (float4*)(S + gw * (long)TKV);
    float4 a = row[lane];
    float4 c = row[lane + 32];

    float m = fmaxf(fmaxf(fmaxf(a.x, a.y), fmaxf(a.z, a.w)),
                    fmaxf(fmaxf(c.x, c.y), fmaxf(c.z, c.w)));
#pragma unroll
    for (int o = 16; o; o >>= 1) m = fmaxf(m, __shfl_xor_sync(0xffffffffu, m, o));

    a.x = __expf(a.x - m); a.y = __expf(a.y - m);
    a.z = __expf(a.z - m); a.w = __expf(a.w - m);
    c.x = __expf(c.x - m); c.y = __expf(c.y - m);
    c.z = __expf(c.z - m); c.w = __expf(c.w - m);

    float s = a.x + a.y + a.z + a.w + c.x + c.y + c.z + c.w;
#pragma unroll
    for (int o = 16; o; o >>= 1) s += __shfl_xor_sync(0xffffffffu, s, o);
    float inv = 1.0f / s;

    a.x *= inv; a.y *= inv; a.z *= inv; a.w *= inv;
    c.x *= inv; c.y *= inv; c.z *= inv; c.w *= inv;
    row[lane] = a;
    row[lane + 32] = c;
}

// ---------------- launch ----------------
extern "C" void kernel_launch(void* const* d_in, const int* in_sizes, int n_in,
                              void* d_out, int out_size)
{
    const float* grid      = (const float*)d_in[0];
    const float* query_pos = (const float*)d_in[1];
    const float* Wq        = (const float*)d_in[2];
    const float* Wk        = (const float*)d_in[3];
    const float* Wv        = (const float*)d_in[4];
    const float* Wo        = (const float*)d_in[5];
    const float* lng_g     = (const float*)d_in[6];
    const float* lng_b     = (const float*)d_in[7];
    const float* lnq_g     = (const float*)d_in[8];
    const float* lnq_b     = (const float*)d_in[9];
    const float* lnm_g     = (const float*)d_in[10];
    const float* lnm_b     = (const float*)d_in[11];
    const float* W1        = (const float*)d_in[12];
    const float* b1        = (const float*)d_in[13];
    const float* W2        = (const float*)d_in[14];
    const float* b2        = (const float*)d_in[15];
    float* out = (float*)d_out;

    float *Kp, *Kn, *V, *qn, *Q, *S, *attn, *x, *xn;
    __half *hb, *WkT, *WvT, *WqT, *WoT, *W1T, *W2T, *VT;
    cudaGetSymbolAddress((void**)&Kp,   g_Kpre);
    cudaGetSymbolAddress((void**)&Kn,   g_Kn);
    cudaGetSymbolAddress((void**)&V,    g_V);
    cudaGetSymbolAddress((void**)&qn,   g_qn);
    cudaGetSymbolAddress((void**)&Q,    g_Q);
    cudaGetSymbolAddress((void**)&S,    g_S);
    cudaGetSymbolAddress((void**)&attn, g_attn);
    cudaGetSymbolAddress((void**)&x,    g_x);
    cudaGetSymbolAddress((void**)&xn,   g_xn);
    cudaGetSymbolAddress((void**)&hb,   g_h);
    cudaGetSymbolAddress((void**)&WkT,  g_WkT);
    cudaGetSymbolAddress((void**)&WvT,  g_WvT);
    cudaGetSymbolAddress((void**)&WqT,  g_WqT);
    cudaGetSymbolAddress((void**)&WoT,  g_WoT);
    cudaGetSymbolAddress((void**)&W1T,  g_W1T);
    cudaGetSymbolAddress((void**)&W2T,  g_W2T);
    cudaGetSymbolAddress((void**)&VT,   g_VT);

    dim3 blk(256);
    const int MG = BB * TKV;       // 4096
    const int MQ = BB * LQ;        // 16384
    const int HD = MULT * SEQ_D;   // 4096

    // 0) transpose weights -> fp16 [N][K]
    transpose_kernel<<<dim3(SEQ_D / 32, GRID_D / 32), blk>>>(Wk, WkT, GRID_D, SEQ_D);
    transpose_kernel<<<dim3(SEQ_D / 32, GRID_D / 32), blk>>>(Wv, WvT, GRID_D, SEQ_D);
    transpose_kernel<<<dim3(SEQ_D / 32, POS_D / 32),  blk>>>(Wq, WqT, POS_D, SEQ_D);
    transpose_kernel<<<dim3(SEQ_D / 32, SEQ_D / 32),  blk>>>(Wo, WoT, SEQ_D, SEQ_D);
    transpose_kernel<<<dim3(HD / 32, SEQ_D / 32),     blk>>>(W1, W1T, SEQ_D, HD);
    transpose_kernel<<<dim3(SEQ_D / 32, HD / 32),     blk>>>(W2, W2T, HD, SEQ_D);

    // 1) Kpre = grid @ Wk ; V = grid @ Wv
    gemm_h<float, __half, float, EPI_NONE, 128>
        <<<dim3(SEQ_D / 128, MG / 128, 1), blk>>>(
        grid, WkT, nullptr, nullptr, Kp, MG, SEQ_D, GRID_D,
        GRID_D, GRID_D, SEQ_D, 0, 0, 0, 0, 0, 0, 1, 1.0f);
    gemm_h<float, __half, float, EPI_NONE, 128>
        <<<dim3(SEQ_D / 128, MG / 128, 1), blk>>>(
        grid, WvT, nullptr, nullptr, V, MG, SEQ_D, GRID_D,
        GRID_D, GRID_D, SEQ_D, 0, 0, 0, 0, 0, 0, 1, 1.0f);

    // 1b) VT = per-head transpose of V (fp16)
    vt_kernel<<<dim3(TKV / 32, HEAD / 32, BB * NH), blk>>>(V, VT);

    // 2) K = LN(Kpre) ; qn = LN(query_pos)
    ln_kernel<<<MG, 256>>>(Kp, lng_g, lng_b, Kn, SEQ_D);
    ln_kernel<<<MQ, 256>>>(query_pos, lnq_g, lnq_b, qn, POS_D);

    // 3) Q = qn @ Wq
    gemm_h<float, __half, float, EPI_NONE, 128>
        <<<dim3(SEQ_D / 128, MQ / 128, 1), blk>>>(
        qn, WqT, nullptr, nullptr, Q, MQ, SEQ_D, POS_D,
        POS_D, POS_D, SEQ_D, 0, 0, 0, 0, 0, 0, 1, 1.0f);

    // 4) scores = (Qh @ Kh^T)/8 : NT GEMM, B=Kn is natively [n=token][k=dim]
    gemm_h<float, float, float, EPI_NONE, 128>
        <<<dim3(TKV / 128, LQ / 128, BB * NH), blk>>>(
        Q, Kn, nullptr, nullptr, S, LQ, TKV, HEAD,
        SEQ_D, SEQ_D, TKV,
        (long)LQ * SEQ_D, (long)HEAD,
        (long)TKV * SEQ_D, (long)HEAD,
        (long)NH * LQ * TKV, (long)LQ * TKV,
        NH, 0.125f);

    // 5) softmax
    softmax_kernel<<<(BB * NH * LQ) / 8, 256>>>(S, (long)BB * NH * LQ);

    // 6) attn = P @ Vh : NT with B=VT[bh][d][t] (fp16)
    gemm_h<float, __half, float, EPI_NONE, 64>
        <<<dim3(HEAD / 64, LQ / 128, BB * NH), blk>>>(
        S, VT, nullptr, nullptr, attn, LQ, HEAD, TKV,
        TKV, TKV, SEQ_D,
        (long)NH * LQ * TKV, (long)LQ * TKV,
        (long)NH * HEAD * TKV, (long)HEAD * TKV,
        (long)LQ * SEQ_D, (long)HEAD,
        NH, 1.0f);

    // 7) x = Q + attn @ Wo
    gemm_h<float, __half, float, EPI_RESID, 128>
        <<<dim3(SEQ_D / 128, MQ / 128, 1), blk>>>(
        attn, WoT, nullptr, Q, x, MQ, SEQ_D, SEQ_D,
        SEQ_D, SEQ_D, SEQ_D, 0, 0, 0, 0, 0, 0, 1, 1.0f);

    // 8) xn = LN(x)
    ln_kernel<<<MQ, 256>>>(x, lnm_g, lnm_b, xn, SEQ_D);

    // 9) hb = gelu(xn @ W1 + b1)  -> fp16
    gemm_h<float, __half, __half, EPI_GELU_BIAS, 128>
        <<<dim3(HD / 128, MQ / 128, 1), blk>>>(
        xn, W1T, b1, nullptr, hb, MQ, HD, SEQ_D,
        SEQ_D, SEQ_D, HD, 0, 0, 0, 0, 0, 0, 1, 1.0f);

    // 10) out = x + hb @ W2 + b2   (A fp16)
    gemm_h<__half, __half, float, EPI_BIAS_RESID, 128>
        <<<dim3(SEQ_D / 128, MQ / 128, 1), blk>>>(
        hb, W2T, b2, x, out, MQ, SEQ_D, HD,
        HD, HD, SEQ_D, 0, 0, 0, 0, 0, 0, 1, 1.0f);
}

// round 8
// speedup vs baseline: 4.9321x; 1.1426x over previous
#include <cuda_runtime.h>
#include <cuda_fp16.h>
#include <math.h>
#include <stdint.h>

// Problem constants
#define BB      16
#define GRID_D  1024
#define SEQ_D   1024
#define POS_D   512
#define NH      16
#define HEAD    64
#define LQ      1024
#define TKV     256
#define MULT    4
#define EPSF    1e-5f

// ---------------- scratch (static device memory) ---------------
__device__ float  g_Kpre[(size_t)BB * TKV * SEQ_D];
__device__ float  g_Kn  [(size_t)BB * TKV * SEQ_D];
__device__ float  g_V   [(size_t)BB * TKV * SEQ_D];
__device__ float  g_qn  [(size_t)BB * LQ * POS_D];
__device__ float  g_Q   [(size_t)BB * LQ * SEQ_D];
__device__ float  g_attn[(size_t)BB * LQ * SEQ_D];
__device__ float  g_x   [(size_t)BB * LQ * SEQ_D];
__device__ float  g_xn  [(size_t)BB * LQ * SEQ_D];
__device__ __half g_h   [(size_t)BB * LQ * MULT * SEQ_D];
// transposed fp16 weights [N][K]
__device__ __half g_WkT [(size_t)SEQ_D * GRID_D];
__device__ __half g_WvT [(size_t)SEQ_D * GRID_D];
__device__ __half g_WqT [(size_t)SEQ_D * POS_D];
__device__ __half g_WoT [(size_t)SEQ_D * SEQ_D];
__device__ __half g_W1T [(size_t)MULT * SEQ_D * SEQ_D];
__device__ __half g_W2T [(size_t)SEQ_D * MULT * SEQ_D];
// V transposed per head: VT[b*NH+h][d=64][t=256], fp16
__device__ __half g_VT  [(size_t)BB * NH * HEAD * TKV];

// ---------------- helpers ----------------
__device__ __forceinline__ float gelu_f(float v) {
    float v3 = v * v * v;
    return 0.5f * v * (1.0f + tanhf(0.7978845608028654f * (v + 0.044715f * v3)));
}
__device__ __forceinline__ uint32_t sptr(const void* p) {
    uint32_t a;
    asm("{ .reg .u64 t; cvta.to.shared.u64 t, %1; cvt.u32.u64 %0, t; }" : "=r"(a) : "l"(p));
    return a;
}
__device__ __forceinline__ uint32_t pack2(float a, float b) {
    __half2 h = __float22half2_rn(make_float2(a, b));
    return *reinterpret_cast<uint32_t*>(&h);
}

#define LDMX4(r0, r1, r2, r3, addr) \
    asm volatile("ldmatrix.sync.aligned.m8n8.x4.shared.b16 {%0,%1,%2,%3}, [%4];" \
                 : "=r"(r0), "=r"(r1), "=r"(r2), "=r"(r3) : "r"(addr))

#define MMA16816(d, a, b) \
    asm volatile("mma.sync.aligned.m16n8k16.row.col.f32.f16.f16.f32 " \
                 "{%0,%1,%2,%3}, {%4,%5,%6,%7}, {%8,%9}, {%0,%1,%2,%3};" \
                 : "+f"((d)[0]), "+f"((d)[1]), "+f"((d)[2]), "+f"((d)[3]) \
                 : "r"((a)[0]), "r"((a)[1]), "r"((a)[2]), "r"((a)[3]), \
                   "r"((b)[0]), "r"((b)[1]))

enum { EPI_NONE = 0, EPI_RESID = 1, EPI_GELU_BIAS = 2, EPI_BIAS_RESID = 3 };

// =================================================================
// fp16 tensor-core GEMM (NT): C[M,N] = alpha * A[M,K] @ BT[N,K]^T (+epi)
// =================================================================
template <typename TA, typename TB, typename TC, int EPI, int BN>
__global__ __launch_bounds__(256)
void gemm_h(const TA* __restrict__ A, const TB* __restrict__ BT,
            const float* __restrict__ bias, const float* __restrict__ res,
            TC* __restrict__ C,
            int M, int N, int K, int lda, int ldb, int ldc, float alpha)
{
    constexpr int BM = 128, BK = 32;
    constexpr int STR = 40;
    constexpr int WN = BN / 2;
    constexpr int NT = BN / 16;
    constexpr int NSA = (BM * 4) / 256;
    constexpr int NSB = (BN * 4) / 256;

    __shared__ __half As[2][BM][STR];
    __shared__ __half Bs[2][BN][STR];

    const int tid  = threadIdx.x;
    const int lane = tid & 31;
    const int warp = tid >> 5;
    const int wm   = warp >> 1;
    const int wn   = warp & 1;
    const int m0   = blockIdx.y * BM;
    const int n0   = blockIdx.x * BN;

    float acc[2][NT][4];
#pragma unroll
    for (int mt = 0; mt < 2; mt++)
#pragma unroll
        for (int nt = 0; nt < NT; nt++)
#pragma unroll
            for (int j = 0; j < 4; j++) acc[mt][nt][j] = 0.0f;

    float4 raF[NSA][2]; uint4 raH[NSA];
    float4 rbF[NSB][2]; uint4 rbH[NSB];

    auto ldgA = [&](int k0) {
#pragma unroll
        for (int i = 0; i < NSA; i++) {
            int s = tid + i * 256, r = s >> 2, cs = s & 3;
            if (sizeof(TA) == 4) {
                const float* p = (const float*)(const void*)A
                               + (size_t)(m0 + r) * lda + k0 + cs * 8;
                raF[i][0] = *(const float4*)p;
                raF[i][1] = *(const float4*)(p + 4);
            } else {
                const __half* p = (const __half*)(const void*)A
                                + (size_t)(m0 + r) * lda + k0 + cs * 8;
                raH[i] = *(const uint4*)p;
            }
        }
    };
    auto ldgB = [&](int k0) {
#pragma unroll
        for (int i = 0; i < NSB; i++) {
            int s = tid + i * 256, r = s >> 2, cs = s & 3;
            if (sizeof(TB) == 4) {
                const float* p = (const float*)(const void*)BT
                               + (size_t)(n0 + r) * ldb + k0 + cs * 8;
                rbF[i][0] = *(const float4*)p;
                rbF[i][1] = *(const float4*)(p + 4);
            } else {
                const __half* p = (const __half*)(const void*)BT
                                + (size_t)(n0 + r) * ldb + k0 + cs * 8;
                rbH[i] = *(const uint4*)p;
            }
        }
    };
    auto stsA = [&](int buf) {
#pragma unroll
        for (int i = 0; i < NSA; i++) {
            int s = tid + i * 256, r = s >> 2, cs = s & 3;
            uint4 u;
            if (sizeof(TA) == 4) {
                u.x = pack2(raF[i][0].x, raF[i][0].y);
                u.y = pack2(raF[i][0].z, raF[i][0].w);
                u.z = pack2(raF[i][1].x, raF[i][1].y);
                u.w = pack2(raF[i][1].z, raF[i][1].w);
            } else u = raH[i];
            *(uint4*)&As[buf][r][cs * 8] = u;
        }
    };
    auto stsB = [&](int buf) {
#pragma unroll
        for (int i = 0; i < NSB; i++) {
            int s = tid + i * 256, r = s >> 2, cs = s & 3;
            uint4 u;
            if (sizeof(TB) == 4) {
                u.x = pack2(rbF[i][0].x, rbF[i][0].y);
                u.y = pack2(rbF[i][0].z, rbF[i][0].w);
                u.z = pack2(rbF[i][1].x, rbF[i][1].y);
                u.w = pack2(rbF[i][1].z, rbF[i][1].w);
            } else u = rbH[i];
            *(uint4*)&Bs[buf][r][cs * 8] = u;
        }
    };

    const int lr = lane & 15;
    const int lc = lane >> 4;

    auto compute = [&](int buf) {
#pragma unroll
        for (int ks = 0; ks < 2; ks++) {
            uint32_t af[2][4];
#pragma unroll
            for (int mt = 0; mt < 2; mt++) {
                uint32_t ad = sptr(&As[buf][wm * 32 + mt * 16 + lr][ks * 16 + lc * 8]);
                LDMX4(af[mt][0], af[mt][1], af[mt][2], af[mt][3], ad);
            }
            uint32_t bf[NT][2];
#pragma unroll
            for (int np = 0; np < NT / 2; np++) {
                uint32_t r0, r1, r2, r3;
                uint32_t bd = sptr(&Bs[buf][wn * WN + np * 16 + lr][ks * 16 + lc * 8]);
                LDMX4(r0, r1, r2, r3, bd);
                bf[np * 2 + 0][0] = r0; bf[np * 2 + 0][1] = r2;
                bf[np * 2 + 1][0] = r1; bf[np * 2 + 1][1] = r3;
            }
#pragma unroll
            for (int mt = 0; mt < 2; mt++)
#pragma unroll
                for (int nt = 0; nt < NT; nt++)
                    MMA16816(acc[mt][nt], af[mt], bf[nt]);
        }
    };

    const int nk = K / BK;
    ldgA(0); ldgB(0); stsA(0); stsB(0);
    __syncthreads();

    for (int it = 0; it < nk; ++it) {
        const int cur = it & 1;
        if (it + 1 < nk) { ldgA((it + 1) * BK); ldgB((it + 1) * BK); }
        compute(cur);
        if (it + 1 < nk) { stsA(cur ^ 1); stsB(cur ^ 1); }
        __syncthreads();
    }

    const int g4 = lane >> 2, t4 = lane & 3;
#pragma unroll
    for (int mt = 0; mt < 2; mt++) {
#pragma unroll
        for (int nt = 0; nt < NT; nt++) {
            int r = m0 + wm * 32 + mt * 16 + g4;
            int c = n0 + wn * WN + nt * 8 + 2 * t4;
#pragma unroll
            for (int half = 0; half < 2; half++) {
                int rr = r + half * 8;
                float2 v = make_float2(acc[mt][nt][half * 2 + 0] * alpha,
                                       acc[mt][nt][half * 2 + 1] * alpha);
                if (EPI == EPI_GELU_BIAS) {
                    float2 bv = *(const float2*)(bias + c);
                    v.x = gelu_f(v.x + bv.x);
                    v.y = gelu_f(v.y + bv.y);
                } else if (EPI == EPI_RESID) {
                    float2 rv = *(const float2*)(res + (size_t)rr * ldc + c);
                    v.x += rv.x; v.y += rv.y;
                } else if (EPI == EPI_BIAS_RESID) {
                    float2 bv = *(const float2*)(bias + c);
                    float2 rv = *(const float2*)(res + (size_t)rr * ldc + c);
                    v.x += bv.x + rv.x; v.y += bv.y + rv.y;
                }
                if (sizeof(TC) == 4) {
                    *(float2*)((float*)(void*)C + (size_t)rr * ldc + c) = v;
                } else {
                    __half2 h = __float22half2_rn(v);
                    *(__half2*)((__half*)(void*)C + (size_t)rr * ldc + c) = h;
                }
            }
        }
    }
}

// =================================================================
// Fused attention: per block = 128 q-rows x one (b,h).
// S = Q K^T * 0.125 -> softmax (in-register) -> O = P V -> attn
// SMEM: Qs[128][72] fp16, Ks[256][72] fp16, Vs[64][264] fp16 (~89 KB)
// 8 warps, each owns m16 rows, full n=256 score row in registers.
// =================================================================
#define FA_QS_OFF 0
#define FA_KS_OFF (128 * 72)
#define FA_VS_OFF (128 * 72 + 256 * 72)
#define FA_SMEM   ((128 * 72 + 256 * 72 + 64 * 264) * 2)

__global__ __launch_bounds__(256, 1)
void fused_attn(const float* __restrict__ Q, const float* __restrict__ Kn,
                const __half* __restrict__ VT, float* __restrict__ attn)
{
    extern __shared__ __half fsm[];
    __half* Qs = fsm + FA_QS_OFF;
    __half* Ks = fsm + FA_KS_OFF;
    __half* Vs = fsm + FA_VS_OFF;

    const int tid  = threadIdx.x;
    const int lane = tid & 31;
    const int warp = tid >> 5;           // 0..7 = m16 tile index
    const int q0   = blockIdx.x * 128;
    const int bh   = blockIdx.y;
    const int b    = bh >> 4;
    const int h    = bh & 15;

    const float* Qg = Q  + ((size_t)b * LQ + q0) * SEQ_D + h * HEAD;
    const float* Kg = Kn + (size_t)b * TKV * SEQ_D + h * HEAD;
    const __half* Vg = VT + (size_t)bh * HEAD * TKV;

    // stage Q: 128 rows x 64 (fp32 -> fp16), 8-float segments
    for (int s = tid; s < 1024; s += 256) {
        int r = s >> 3, c8 = (s & 7) * 8;
        const float* p = Qg + (size_t)r * SEQ_D + c8;
        float4 v0 = *(const float4*)p, v1 = *(const float4*)(p + 4);
        uint4 u = { pack2(v0.x, v0.y), pack2(v0.z, v0.w),
                    pack2(v1.x, v1.y), pack2(v1.z, v1.w) };
        *(uint4*)&Qs[r * 72 + c8] = u;
    }
    // stage K: 256 rows x 64
    for (int s = tid; s < 2048; s += 256) {
        int r = s >> 3, c8 = (s & 7) * 8;
        const float* p = Kg + (size_t)r * SEQ_D + c8;
        float4 v0 = *(const float4*)p, v1 = *(const float4*)(p + 4);
        uint4 u = { pack2(v0.x, v0.y), pack2(v0.z, v0.w),
                    pack2(v1.x, v1.y), pack2(v1.z, v1.w) };
        *(uint4*)&Ks[r * 72 + c8] = u;
    }
    // stage V (already fp16): 64 rows x 256 halves = 2048 8-half segments
    for (int s = tid; s < 2048; s += 256) {
        int r = s >> 5, c8 = (s & 31) * 8;
        *(uint4*)&Vs[r * 264 + c8] = *(const uint4*)(Vg + (size_t)r * TKV + c8);
    }
    __syncthreads();

    const int lr = lane & 15;
    const int lc = lane >> 4;
    const int g4 = lane >> 2;
    const int t4 = lane & 3;

    // ---- S = Q K^T ----
    float acc[32][4];
#pragma unroll
    for (int nt = 0; nt < 32; nt++)
#pragma unroll
        for (int j = 0; j < 4; j++) acc[nt][j] = 0.0f;

#pragma unroll
    for (int ks = 0; ks < 4; ks++) {
        uint32_t af[4];
        LDMX4(af[0], af[1], af[2], af[3],
              sptr(&Qs[(warp * 16 + lr) * 72 + ks * 16 + lc * 8]));
#pragma unroll
        for (int np = 0; np < 16; np++) {
            uint32_t r0, r1, r2, r3;
            LDMX4(r0, r1, r2, r3,
                  sptr(&Ks[(np * 16 + lr) * 72 + ks * 16 + lc * 8]));
            uint32_t b0[2] = { r0, r2 };
            uint32_t b1[2] = { r1, r3 };
            MMA16816(acc[np * 2 + 0], af, b0);
            MMA16816(acc[np * 2 + 1], af, b1);
        }
    }

    // ---- softmax over 256 cols (rows g4 and g4+8 of this warp's m16) ----
    float mx0 = -1e30f, mx1 = -1e30f;
#pragma unroll
    for (int nt = 0; nt < 32; nt++) {
#pragma unroll
        for (int j = 0; j < 4; j++) acc[nt][j] *= 0.125f;
        mx0 = fmaxf(mx0, fmaxf(acc[nt][0], acc[nt][1]));
        mx1 = fmaxf(mx1, fmaxf(acc[nt][2], acc[nt][3]));
    }
    mx0 = fmaxf(mx0, __shfl_xor_sync(0xffffffffu, mx0, 1));
    mx0 = fmaxf(mx0, __shfl_xor_sync(0xffffffffu, mx0, 2));
    mx1 = fmaxf(mx1, __shfl_xor_sync(0xffffffffu, mx1, 1));
    mx1 = fmaxf(mx1, __shfl_xor_sync(0xffffffffu, mx1, 2));

    float s0 = 0.0f, s1 = 0.0f;
#pragma unroll
    for (int nt = 0; nt < 32; nt++) {
        acc[nt][0] = __expf(acc[nt][0] - mx0);
        acc[nt][1] = __expf(acc[nt][1] - mx0);
        acc[nt][2] = __expf(acc[nt][2] - mx1);
        acc[nt][3] = __expf(acc[nt][3] - mx1);
        s0 += acc[nt][0] + acc[nt][1];
        s1 += acc[nt][2] + acc[nt][3];
    }
    s0 += __shfl_xor_sync(0xffffffffu, s0, 1);
    s0 += __shfl_xor_sync(0xffffffffu, s0, 2);
    s1 += __shfl_xor_sync(0xffffffffu, s1, 1);
    s1 += __shfl_xor_sync(0xffffffffu, s1, 2);
    const float inv0 = 1.0f / s0;
    const float inv1 = 1.0f / s1;

    // ---- O = P V  (P from acc regs as A-fragments) ----
    float oacc[8][4];
#pragma unroll
    for (int nt = 0; nt < 8; nt++)
#pragma unroll
        for (int j = 0; j < 4; j++) oacc[nt][j] = 0.0f;

#pragma unroll
    for (int kc = 0; kc < 16; kc++) {
        uint32_t af[4];
        af[0] = pack2(acc[2 * kc][0],     acc[2 * kc][1]);
        af[1] = pack2(acc[2 * kc][2],     acc[2 * kc][3]);
        af[2] = pack2(acc[2 * kc + 1][0], acc[2 * kc + 1][1]);
        af[3] = pack2(acc[2 * kc + 1][2], acc[2 * kc + 1][3]);
#pragma unroll
        for (int np = 0; np < 4; np++) {
            uint32_t r0, r1, r2, r3;
            LDMX4(r0, r1, r2, r3,
                  sptr(&Vs[(np * 16 + lr) * 264 + kc * 16 + lc * 8]));
            uint32_t b0[2] = { r0, r2 };
            uint32_t b1[2] = { r1, r3 };
            MMA16816(oacc[np * 2 + 0], af, b0);
            MMA16816(oacc[np * 2 + 1], af, b1);
        }
    }

    // ---- write attn[b][q][h*64+d], normalized ----
    float* Og = attn + ((size_t)b * LQ + q0 + warp * 16) * SEQ_D + h * HEAD;
#pragma unroll
    for (int nt = 0; nt < 8; nt++) {
        int c = nt * 8 + 2 * t4;
        float2 v0 = make_float2(oacc[nt][0] * inv0, oacc[nt][1] * inv0);
        float2 v1 = make_float2(oacc[nt][2] * inv1, oacc[nt][3] * inv1);
        *(float2*)(Og + (size_t)g4 * SEQ_D + c)       = v0;
        *(float2*)(Og + (size_t)(g4 + 8) * SEQ_D + c) = v1;
    }
}

// ---------------- weight transpose: WT[n][k] = half(W[k][n]) ----------------
__global__ __launch_bounds__(256)
void transpose_kernel(const float* __restrict__ W, __half* __restrict__ WT,
                      int K, int N)
{
    __shared__ float t[32][33];
    int n0 = blockIdx.x * 32, k0 = blockIdx.y * 32;
    int tx = threadIdx.x & 31, ty = threadIdx.x >> 5;
#pragma unroll
    for (int i = 0; i < 32; i += 8)
        t[ty + i][tx] = W[(size_t)(k0 + ty + i) * N + n0 + tx];
    __syncthreads();
#pragma unroll
    for (int i = 0; i < 32; i += 8)
        WT[(size_t)(n0 + ty + i) * K + k0 + tx] = __float2half_rn(t[tx][ty + i]);
}

// ---------------- V transpose per head: VT[bh][d][t] ----------------
__global__ __launch_bounds__(256)
void vt_kernel(const float* __restrict__ V, __half* __restrict__ VT)
{
    __shared__ float t[32][33];
    int t0 = blockIdx.x * 32;
    int d0 = blockIdx.y * 32;
    int bh = blockIdx.z;
    int b = bh / NH, h = bh % NH;
    int tx = threadIdx.x & 31, ty = threadIdx.x >> 5;
#pragma unroll
    for (int i = 0; i < 32; i += 8)
        t[ty + i][tx] = V[((size_t)b * TKV + t0 + ty + i) * SEQ_D + h * HEAD + d0 + tx];
    __syncthreads();
#pragma unroll
    for (int i = 0; i < 32; i += 8)
        VT[((size_t)bh * HEAD + d0 + ty + i) * TKV + t0 + tx] =
            __float2half_rn(t[tx][ty + i]);
}

// ---------------- LayerNorm ----------------
__global__ __launch_bounds__(256)
void ln_kernel(const float* __restrict__ X, const float* __restrict__ g,
               const float* __restrict__ b, float* __restrict__ Y, int D)
{
    long row = blockIdx.x;
    const float4* x4 = (const float4*)(X + row * (long)D);
    float4*       y4 = (float4*)(Y + row * (long)D);
    const float4* g4 = (const float4*)g;
    const float4* b4 = (const float4*)b;
    int n4 = D >> 2;

    float s = 0.0f, s2 = 0.0f;
    for (int i = threadIdx.x; i < n4; i += 256) {
        float4 v = x4[i];
        s  += v.x + v.y + v.z + v.w;
        s2 += v.x * v.x + v.y * v.y + v.z * v.z + v.w * v.w;
    }
#pragma unroll
    for (int o = 16; o; o >>= 1) {
        s  += __shfl_xor_sync(0xffffffffu, s, o);
        s2 += __shfl_xor_sync(0xffffffffu, s2, o);
    }
    __shared__ float sh[16];
    int w = threadIdx.x >> 5, lane = threadIdx.x & 31;
    if (lane == 0) { sh[w] = s; sh[w + 8] = s2; }
    __syncthreads();
    if (threadIdx.x < 32) {
        float a = (threadIdx.x < 8) ? sh[threadIdx.x] : 0.0f;
        float c = (threadIdx.x < 8) ? sh[threadIdx.x + 8] : 0.0f;
#pragma unroll
        for (int o = 16; o; o >>= 1) {
            a += __shfl_xor_sync(0xffffffffu, a, o);
            c += __shfl_xor_sync(0xffffffffu, c, o);
        }
        if (threadIdx.x == 0) { sh[0] = a; sh[1] = c; }
    }
    __syncthreads();
    float invD = 1.0f / (float)D;
    float mu   = sh[0] * invD;
    float var  = sh[1] * invD - mu * mu;
    float rstd = rsqrtf(var + EPSF);

    for (int i = threadIdx.x; i < n4; i += 256) {
        float4 v = x4[i], gg = g4[i], bb = b4[i];
        v.x = (v.x - mu) * rstd * gg.x + bb.x;
        v.y = (v.y - mu) * rstd * gg.y + bb.y;
        v.z = (v.z - mu) * rstd * gg.z + bb.z;
        v.w = (v.w - mu) * rstd * gg.w + bb.w;
        y4[i] = v;
    }
}

// ---------------- launch ----------------
extern "C" void kernel_launch(void* const* d_in, const int* in_sizes, int n_in,
                              void* d_out, int out_size)
{
    const float* grid      = (const float*)d_in[0];
    const float* query_pos = (const float*)d_in[1];
    const float* Wq        = (const float*)d_in[2];
    const float* Wk        = (const float*)d_in[3];
    const float* Wv        = (const float*)d_in[4];
    const float* Wo        = (const float*)d_in[5];
    const float* lng_g     = (const float*)d_in[6];
    const float* lng_b     = (const float*)d_in[7];
    const float* lnq_g     = (const float*)d_in[8];
    const float* lnq_b     = (const float*)d_in[9];
    const float* lnm_g     = (const float*)d_in[10];
    const float* lnm_b     = (const float*)d_in[11];
    const float* W1        = (const float*)d_in[12];
    const float* b1        = (const float*)d_in[13];
    const float* W2        = (const float*)d_in[14];
    const float* b2        = (const float*)d_in[15];
    float* out = (float*)d_out;

    float *Kp, *Kn, *V, *qn, *Q, *attn, *x, *xn;
    __half *hb, *WkT, *WvT, *WqT, *WoT, *W1T, *W2T, *VT;
    cudaGetSymbolAddress((void**)&Kp,   g_Kpre);
    cudaGetSymbolAddress((void**)&Kn,   g_Kn);
    cudaGetSymbolAddress((void**)&V,    g_V);
    cudaGetSymbolAddress((void**)&qn,   g_qn);
    cudaGetSymbolAddress((void**)&Q,    g_Q);
    cudaGetSymbolAddress((void**)&attn, g_attn);
    cudaGetSymbolAddress((void**)&x,    g_x);
    cudaGetSymbolAddress((void**)&xn,   g_xn);
    cudaGetSymbolAddress((void**)&hb,   g_h);
    cudaGetSymbolAddress((void**)&WkT,  g_WkT);
    cudaGetSymbolAddress((void**)&WvT,  g_WvT);
    cudaGetSymbolAddress((void**)&WqT,  g_WqT);
    cudaGetSymbolAddress((void**)&WoT,  g_WoT);
    cudaGetSymbolAddress((void**)&W1T,  g_W1T);
    cudaGetSymbolAddress((void**)&W2T,  g_W2T);
    cudaGetSymbolAddress((void**)&VT,   g_VT);

    cudaFuncSetAttribute(fused_attn,
        cudaFuncAttributeMaxDynamicSharedMemorySize, FA_SMEM);

    dim3 blk(256);
    const int MG = BB * TKV;       // 4096
    const int MQ = BB * LQ;        // 16384
    const int HD = MULT * SEQ_D;   // 4096

    // 0) transpose weights -> fp16 [N][K]
    transpose_kernel<<<dim3(SEQ_D / 32, GRID_D / 32), blk>>>(Wk, WkT, GRID_D, SEQ_D);
    transpose_kernel<<<dim3(SEQ_D / 32, GRID_D / 32), blk>>>(Wv, WvT, GRID_D, SEQ_D);
    transpose_kernel<<<dim3(SEQ_D / 32, POS_D / 32),  blk>>>(Wq, WqT, POS_D, SEQ_D);
    transpose_kernel<<<dim3(SEQ_D / 32, SEQ_D / 32),  blk>>>(Wo, WoT, SEQ_D, SEQ_D);
    transpose_kernel<<<dim3(HD / 32, SEQ_D / 32),     blk>>>(W1, W1T, SEQ_D, HD);
    transpose_kernel<<<dim3(SEQ_D / 32, HD / 32),     blk>>>(W2, W2T, HD, SEQ_D);

    // 1) Kpre = grid @ Wk ; V = grid @ Wv
    gemm_h<float, __half, float, EPI_NONE, 128>
        <<<dim3(SEQ_D / 128, MG / 128), blk>>>(
        grid, WkT, nullptr, nullptr, Kp, MG, SEQ_D, GRID_D,
        GRID_D, GRID_D, SEQ_D, 1.0f);
    gemm_h<float, __half, float, EPI_NONE, 128>
        <<<dim3(SEQ_D / 128, MG / 128), blk>>>(
        grid, WvT, nullptr, nullptr, V, MG, SEQ_D, GRID_D,
        GRID_D, GRID_D, SEQ_D, 1.0f);

    // 1b) VT = per-head transpose of V (fp16)
    vt_kernel<<<dim3(TKV / 32, HEAD / 32, BB * NH), blk>>>(V, VT);

    // 2) K = LN(Kpre) ; qn = LN(query_pos)
    ln_kernel<<<MG, 256>>>(Kp, lng_g, lng_b, Kn, SEQ_D);
    ln_kernel<<<MQ, 256>>>(query_pos, lnq_g, lnq_b, qn, POS_D);

    // 3) Q = qn @ Wq
    gemm_h<float, __half, float, EPI_NONE, 128>
        <<<dim3(SEQ_D / 128, MQ / 128), blk>>>(
        qn, WqT, nullptr, nullptr, Q, MQ, SEQ_D, POS_D,
        POS_D, POS_D, SEQ_D, 1.0f);

    // 4-6) fused attention: S = QK^T/8, softmax, O = PV
    fused_attn<<<dim3(LQ / 128, BB * NH), blk, FA_SMEM>>>(Q, Kn, VT, attn);

    // 7) x = Q + attn @ Wo
    gemm_h<float, __half, float, EPI_RESID, 128>
        <<<dim3(SEQ_D / 128, MQ / 128), blk>>>(
        attn, WoT, nullptr, Q, x, MQ, SEQ_D, SEQ_D,
        SEQ_D, SEQ_D, SEQ_D, 1.0f);

    // 8) xn = LN(x)
    ln_kernel<<<MQ, 256>>>(x, lnm_g, lnm_b, xn, SEQ_D);

    // 9) hb = gelu(xn @ W1 + b1)  -> fp16
    gemm_h<float, __half, __half, EPI_GELU_BIAS, 128>
        <<<dim3(HD / 128, MQ / 128), blk>>>(
        xn, W1T, b1, nullptr, hb, MQ, HD, SEQ_D,
        SEQ_D, SEQ_D, HD, 1.0f);

    // 10) out = x + hb @ W2 + b2   (A fp16)
    gemm_h<__half, __half, float, EPI_BIAS_RESID, 128>
        <<<dim3(SEQ_D / 128, MQ / 128), blk>>>(
        hb, W2T, b2, x, out, MQ, SEQ_D, HD,
        HD, HD, SEQ_D, 1.0f);
}

// round 9
// speedup vs baseline: 4.9554x; 1.0047x over previous
#include <cuda_runtime.h>
#include <cuda_fp16.h>
#include <math.h>
#include <stdint.h>

// Problem constants
#define BB      16
#define GRID_D  1024
#define SEQ_D   1024
#define POS_D   512
#define NH      16
#define HEAD    64
#define LQ      1024
#define TKV     256
#define MULT    4
#define EPSF    1e-5f

// ---------------- scratch (static device memory) ---------------
__device__ __half g_gridh[(size_t)BB * TKV * GRID_D];         // fp16 copy of grid
__device__ float  g_Kpre[(size_t)BB * TKV * SEQ_D];
__device__ __half g_Kn  [(size_t)BB * TKV * SEQ_D];           // fp16 LN output
__device__ float  g_V   [(size_t)BB * TKV * SEQ_D];
__device__ __half g_qn  [(size_t)BB * LQ * POS_D];            // fp16 LN output
__device__ float  g_Q   [(size_t)BB * LQ * SEQ_D];
__device__ __half g_attn[(size_t)BB * LQ * SEQ_D];            // fp16 attn output
__device__ float  g_x   [(size_t)BB * LQ * SEQ_D];
__device__ __half g_xn  [(size_t)BB * LQ * SEQ_D];            // fp16 LN output
__device__ __half g_h   [(size_t)BB * LQ * MULT * SEQ_D];
// transposed fp16 weights [N][K]
__device__ __half g_WkT [(size_t)SEQ_D * GRID_D];
__device__ __half g_WvT [(size_t)SEQ_D * GRID_D];
__device__ __half g_WqT [(size_t)SEQ_D * POS_D];
__device__ __half g_WoT [(size_t)SEQ_D * SEQ_D];
__device__ __half g_W1T [(size_t)MULT * SEQ_D * SEQ_D];
__device__ __half g_W2T [(size_t)SEQ_D * MULT * SEQ_D];
// V transposed per head: VT[b*NH+h][d=64][t=256], fp16
__device__ __half g_VT  [(size_t)BB * NH * HEAD * TKV];

// ---------------- helpers ----------------
__device__ __forceinline__ float gelu_f(float v) {
    float v3 = v * v * v;
    return 0.5f * v * (1.0f + tanhf(0.7978845608028654f * (v + 0.044715f * v3)));
}
__device__ __forceinline__ uint32_t sptr(const void* p) {
    uint32_t a;
    asm("{ .reg .u64 t; cvta.to.shared.u64 t, %1; cvt.u32.u64 %0, t; }" : "=r"(a) : "l"(p));
    return a;
}
__device__ __forceinline__ uint32_t pack2(float a, float b) {
    __half2 h = __float22half2_rn(make_float2(a, b));
    return *reinterpret_cast<uint32_t*>(&h);
}

#define CP_ASYNC16(dst, src) \
    asm volatile("cp.async.cg.shared.global [%0], [%1], 16;" \
                 :: "r"(dst), "l"(src) : "memory")
#define CP_COMMIT() asm volatile("cp.async.commit_group;" ::: "memory")
#define CP_WAIT0()  asm volatile("cp.async.wait_group 0;" ::: "memory")

#define LDMX4(r0, r1, r2, r3, addr) \
    asm volatile("ldmatrix.sync.aligned.m8n8.x4.shared.b16 {%0,%1,%2,%3}, [%4];" \
                 : "=r"(r0), "=r"(r1), "=r"(r2), "=r"(r3) : "r"(addr))

#define MMA16816(d, a, b) \
    asm volatile("mma.sync.aligned.m16n8k16.row.col.f32.f16.f16.f32 " \
                 "{%0,%1,%2,%3}, {%4,%5,%6,%7}, {%8,%9}, {%0,%1,%2,%3};" \
                 : "+f"((d)[0]), "+f"((d)[1]), "+f"((d)[2]), "+f"((d)[3]) \
                 : "r"((a)[0]), "r"((a)[1]), "r"((a)[2]), "r"((a)[3]), \
                   "r"((b)[0]), "r"((b)[1]))

enum { EPI_NONE = 0, EPI_RESID = 1, EPI_GELU_BIAS = 2, EPI_BIAS_RESID = 3 };

// =================================================================
// fp16 tensor-core GEMM (NT): C[M,N] = alpha * A[M,K] @ BT[N,K]^T (+epi)
// All operands fp16; cp.async staging; double-buffered; fp32 accum.
// =================================================================
template <typename TC, int EPI, int BN>
__global__ __launch_bounds__(256, 2)
void gemm_h(const __half* __restrict__ A, const __half* __restrict__ BT,
            const float* __restrict__ bias, const float* __restrict__ res,
            TC* __restrict__ C,
            int M, int N, int K, int lda, int ldb, int ldc, float alpha)
{
    constexpr int BM = 128, BK = 32;
    constexpr int STR = 40;
    constexpr int WN = BN / 2;
    constexpr int NT = BN / 16;
    constexpr int NSA = (BM * 4) / 256;   // 2
    constexpr int NSB = (BN * 4) / 256;   // 2 or 1

    __shared__ __half As[2][BM][STR];
    __shared__ __half Bs[2][BN][STR];

    const int tid  = threadIdx.x;
    const int lane = tid & 31;
    const int warp = tid >> 5;
    const int wm   = warp >> 1;
    const int wn   = warp & 1;
    const int m0   = blockIdx.y * BM;
    const int n0   = blockIdx.x * BN;

    float acc[2][NT][4];
#pragma unroll
    for (int mt = 0; mt < 2; mt++)
#pragma unroll
        for (int nt = 0; nt < NT; nt++)
#pragma unroll
            for (int j = 0; j < 4; j++) acc[mt][nt][j] = 0.0f;

    auto issue = [&](int buf, int k0) {
#pragma unroll
        for (int i = 0; i < NSA; i++) {
            int s = tid + i * 256, r = s >> 2, cs = s & 3;
            CP_ASYNC16(sptr(&As[buf][r][cs * 8]),
                       A + (size_t)(m0 + r) * lda + k0 + cs * 8);
        }
#pragma unroll
        for (int i = 0; i < NSB; i++) {
            int s = tid + i * 256, r = s >> 2, cs = s & 3;
            CP_ASYNC16(sptr(&Bs[buf][r][cs * 8]),
                       BT + (size_t)(n0 + r) * ldb + k0 + cs * 8);
        }
        CP_COMMIT();
    };

    const int lr = lane & 15;
    const int lc = lane >> 4;

    auto compute = [&](int buf) {
#pragma unroll
        for (int ks = 0; ks < 2; ks++) {
            uint32_t af[2][4];
#pragma unroll
            for (int mt = 0; mt < 2; mt++) {
                uint32_t ad = sptr(&As[buf][wm * 32 + mt * 16 + lr][ks * 16 + lc * 8]);
                LDMX4(af[mt][0], af[mt][1], af[mt][2], af[mt][3], ad);
            }
            uint32_t bf[NT][2];
#pragma unroll
            for (int np = 0; np < NT / 2; np++) {
                uint32_t r0, r1, r2, r3;
                uint32_t bd = sptr(&Bs[buf][wn * WN + np * 16 + lr][ks * 16 + lc * 8]);
                LDMX4(r0, r1, r2, r3, bd);
                bf[np * 2 + 0][0] = r0; bf[np * 2 + 0][1] = r2;
                bf[np * 2 + 1][0] = r1; bf[np * 2 + 1][1] = r3;
            }
#pragma unroll
            for (int mt = 0; mt < 2; mt++)
#pragma unroll
                for (int nt = 0; nt < NT; nt++)
                    MMA16816(acc[mt][nt], af[mt], bf[nt]);
        }
    };

    const int nk = K / BK;
    issue(0, 0);
    for (int it = 0; it < nk; ++it) {
        const int cur = it & 1;
        CP_WAIT0();
        __syncthreads();
        if (it + 1 < nk) issue(cur ^ 1, (it + 1) * BK);
        compute(cur);
    }

    const int g4 = lane >> 2, t4 = lane & 3;
#pragma unroll
    for (int mt = 0; mt < 2; mt++) {
#pragma unroll
        for (int nt = 0; nt < NT; nt++) {
            int r = m0 + wm * 32 + mt * 16 + g4;
            int c = n0 + wn * WN + nt * 8 + 2 * t4;
#pragma unroll
            for (int half = 0; half < 2; half++) {
                int rr = r + half * 8;
                float2 v = make_float2(acc[mt][nt][half * 2 + 0] * alpha,
                                       acc[mt][nt][half * 2 + 1] * alpha);
                if (EPI == EPI_GELU_BIAS) {
                    float2 bv = *(const float2*)(bias + c);
                    v.x = gelu_f(v.x + bv.x);
                    v.y = gelu_f(v.y + bv.y);
                } else if (EPI == EPI_RESID) {
                    float2 rv = *(const float2*)(res + (size_t)rr * ldc + c);
                    v.x += rv.x; v.y += rv.y;
                } else if (EPI == EPI_BIAS_RESID) {
                    float2 bv = *(const float2*)(bias + c);
                    float2 rv = *(const float2*)(res + (size_t)rr * ldc + c);
                    v.x += bv.x + rv.x; v.y += bv.y + rv.y;
                }
                if (sizeof(TC) == 4) {
                    *(float2*)((float*)(void*)C + (size_t)rr * ldc + c) = v;
                } else {
                    __half2 h = __float22half2_rn(v);
                    *(__half2*)((__half*)(void*)C + (size_t)rr * ldc + c) = h;
                }
            }
        }
    }
}

// =================================================================
// Fused attention: per block = 128 q-rows x one (b,h).
// Q fp32, Kn fp16, VT fp16 in; attn fp16 out.
// =================================================================
#define FA_QS_OFF 0
#define FA_KS_OFF (128 * 72)
#define FA_VS_OFF (128 * 72 + 256 * 72)
#define FA_SMEM   ((128 * 72 + 256 * 72 + 64 * 264) * 2)

__global__ __launch_bounds__(256, 1)
void fused_attn(const float* __restrict__ Q, const __half* __restrict__ Kn,
                const __half* __restrict__ VT, __half* __restrict__ attn)
{
    extern __shared__ __half fsm[];
    __half* Qs = fsm + FA_QS_OFF;
    __half* Ks = fsm + FA_KS_OFF;
    __half* Vs = fsm + FA_VS_OFF;

    const int tid  = threadIdx.x;
    const int lane = tid & 31;
    const int warp = tid >> 5;
    const int q0   = blockIdx.x * 128;
    const int bh   = blockIdx.y;
    const int b    = bh >> 4;
    const int h    = bh & 15;

    const float*  Qg = Q  + ((size_t)b * LQ + q0) * SEQ_D + h * HEAD;
    const __half* Kg = Kn + (size_t)b * TKV * SEQ_D + h * HEAD;
    const __half* Vg = VT + (size_t)bh * HEAD * TKV;

    // stage Q: 128 rows x 64 (fp32 -> fp16)
    for (int s = tid; s < 1024; s += 256) {
        int r = s >> 3, c8 = (s & 7) * 8;
        const float* p = Qg + (size_t)r * SEQ_D + c8;
        float4 v0 = *(const float4*)p, v1 = *(const float4*)(p + 4);
        uint4 u = { pack2(v0.x, v0.y), pack2(v0.z, v0.w),
                    pack2(v1.x, v1.y), pack2(v1.z, v1.w) };
        *(uint4*)&Qs[r * 72 + c8] = u;
    }
    // stage K (fp16 direct): 256 rows x 64 halves = 2048 8-half segments
    for (int s = tid; s < 2048; s += 256) {
        int r = s >> 3, c8 = (s & 7) * 8;
        *(uint4*)&Ks[r * 72 + c8] = *(const uint4*)(Kg + (size_t)r * SEQ_D + c8);
    }
    // stage V (fp16): 64 rows x 256 halves = 2048 8-half segments
    for (int s = tid; s < 2048; s += 256) {
        int r = s >> 5, c8 = (s & 31) * 8;
        *(uint4*)&Vs[r * 264 + c8] = *(const uint4*)(Vg + (size_t)r * TKV + c8);
    }
    __syncthreads();

    const int lr = lane & 15;
    const int lc = lane >> 4;
    const int g4 = lane >> 2;
    const int t4 = lane & 3;

    // ---- S = Q K^T ----
    float acc[32][4];
#pragma unroll
    for (int nt = 0; nt < 32; nt++)
#pragma unroll
        for (int j = 0; j < 4; j++) acc[nt][j] = 0.0f;

#pragma unroll
    for (int ks = 0; ks < 4; ks++) {
        uint32_t af[4];
        LDMX4(af[0], af[1], af[2], af[3],
              sptr(&Qs[(warp * 16 + lr) * 72 + ks * 16 + lc * 8]));
#pragma unroll
        for (int np = 0; np < 16; np++) {
            uint32_t r0, r1, r2, r3;
            LDMX4(r0, r1, r2, r3,
                  sptr(&Ks[(np * 16 + lr) * 72 + ks * 16 + lc * 8]));
            uint32_t b0[2] = { r0, r2 };
            uint32_t b1[2] = { r1, r3 };
            MMA16816(acc[np * 2 + 0], af, b0);
            MMA16816(acc[np * 2 + 1], af, b1);
        }
    }

    // ---- softmax over 256 cols ----
    float mx0 = -1e30f, mx1 = -1e30f;
#pragma unroll
    for (int nt = 0; nt < 32; nt++) {
#pragma unroll
        for (int j = 0; j < 4; j++) acc[nt][j] *= 0.125f;
        mx0 = fmaxf(mx0, fmaxf(acc[nt][0], acc[nt][1]));
        mx1 = fmaxf(mx1, fmaxf(acc[nt][2], acc[nt][3]));
    }
    mx0 = fmaxf(mx0, __shfl_xor_sync(0xffffffffu, mx0, 1));
    mx0 = fmaxf(mx0, __shfl_xor_sync(0xffffffffu, mx0, 2));
    mx1 = fmaxf(mx1, __shfl_xor_sync(0xffffffffu, mx1, 1));
    mx1 = fmaxf(mx1, __shfl_xor_sync(0xffffffffu, mx1, 2));

    float s0 = 0.0f, s1 = 0.0f;
#pragma unroll
    for (int nt = 0; nt < 32; nt++) {
        acc[nt][0] = __expf(acc[nt][0] - mx0);
        acc[nt][1] = __expf(acc[nt][1] - mx0);
        acc[nt][2] = __expf(acc[nt][2] - mx1);
        acc[nt][3] = __expf(acc[nt][3] - mx1);
        s0 += acc[nt][0] + acc[nt][1];
        s1 += acc[nt][2] + acc[nt][3];
    }
    s0 += __shfl_xor_sync(0xffffffffu, s0, 1);
    s0 += __shfl_xor_sync(0xffffffffu, s0, 2);
    s1 += __shfl_xor_sync(0xffffffffu, s1, 1);
    s1 += __shfl_xor_sync(0xffffffffu, s1, 2);
    const float inv0 = 1.0f / s0;
    const float inv1 = 1.0f / s1;

    // ---- O = P V ----
    float oacc[8][4];
#pragma unroll
    for (int nt = 0; nt < 8; nt++)
#pragma unroll
        for (int j = 0; j < 4; j++) oacc[nt][j] = 0.0f;

#pragma unroll
    for (int kc = 0; kc < 16; kc++) {
        uint32_t af[4];
        af[0] = pack2(acc[2 * kc][0],     acc[2 * kc][1]);
        af[1] = pack2(acc[2 * kc][2],     acc[2 * kc][3]);
        af[2] = pack2(acc[2 * kc + 1][0], acc[2 * kc + 1][1]);
        af[3] = pack2(acc[2 * kc + 1][2], acc[2 * kc + 1][3]);
#pragma unroll
        for (int np = 0; np < 4; np++) {
            uint32_t r0, r1, r2, r3;
            LDMX4(r0, r1, r2, r3,
                  sptr(&Vs[(np * 16 + lr) * 264 + kc * 16 + lc * 8]));
            uint32_t b0[2] = { r0, r2 };
            uint32_t b1[2] = { r1, r3 };
            MMA16816(oacc[np * 2 + 0], af, b0);
            MMA16816(oacc[np * 2 + 1], af, b1);
        }
    }

    // ---- write attn (fp16), normalized ----
    __half* Og = attn + ((size_t)b * LQ + q0 + warp * 16) * SEQ_D + h * HEAD;
#pragma unroll
    for (int nt = 0; nt < 8; nt++) {
        int c = nt * 8 + 2 * t4;
        float2 v0 = make_float2(oacc[nt][0] * inv0, oacc[nt][1] * inv0);
        float2 v1 = make_float2(oacc[nt][2] * inv1, oacc[nt][3] * inv1);
        *(__half2*)(Og + (size_t)g4 * SEQ_D + c)       = __float22half2_rn(v0);
        *(__half2*)(Og + (size_t)(g4 + 8) * SEQ_D + c) = __float22half2_rn(v1);
    }
}

// ---------------- fp32 -> fp16 elementwise ----------------
__global__ __launch_bounds__(256)
void f2h_kernel(const float* __restrict__ X, __half* __restrict__ Y)
{
    size_t s = (size_t)blockIdx.x * 256 + threadIdx.x;   // 8 floats each
    const float* p = X + s * 8;
    float4 v0 = *(const float4*)p, v1 = *(const float4*)(p + 4);
    uint4 u = { pack2(v0.x, v0.y), pack2(v0.z, v0.w),
                pack2(v1.x, v1.y), pack2(v1.z, v1.w) };
    *(uint4*)(Y + s * 8) = u;
}

// ---------------- weight transpose: WT[n][k] = half(W[k][n]) ----------------
__global__ __launch_bounds__(256)
void transpose_kernel(const float* __restrict__ W, __half* __restrict__ WT,
                      int K, int N)
{
    __shared__ float t[32][33];
    int n0 = blockIdx.x * 32, k0 = blockIdx.y * 32;
    int tx = threadIdx.x & 31, ty = threadIdx.x >> 5;
#pragma unroll
    for (int i = 0; i < 32; i += 8)
        t[ty + i][tx] = W[(size_t)(k0 + ty + i) * N + n0 + tx];
    __syncthreads();
#pragma unroll
    for (int i = 0; i < 32; i += 8)
        WT[(size_t)(n0 + ty + i) * K + k0 + tx] = __float2half_rn(t[tx][ty + i]);
}

// ---------------- V transpose per head: VT[bh][d][t] ----------------
__global__ __launch_bounds__(256)
void vt_kernel(const float* __restrict__ V, __half* __restrict__ VT)
{
    __shared__ float t[32][33];
    int t0 = blockIdx.x * 32;
    int d0 = blockIdx.y * 32;
    int bh = blockIdx.z;
    int b = bh / NH, h = bh % NH;
    int tx = threadIdx.x & 31, ty = threadIdx.x >> 5;
#pragma unroll
    for (int i = 0; i < 32; i += 8)
        t[ty + i][tx] = V[((size_t)b * TKV + t0 + ty + i) * SEQ_D + h * HEAD + d0 + tx];
    __syncthreads();
#pragma unroll
    for (int i = 0; i < 32; i += 8)
        VT[((size_t)bh * HEAD + d0 + ty + i) * TKV + t0 + tx] =
            __float2half_rn(t[tx][ty + i]);
}

// ---------------- LayerNorm (templated output type) ----------------
template <typename TOUT>
__global__ __launch_bounds__(256)
void ln_kernel(const float* __restrict__ X, const float* __restrict__ g,
               const float* __restrict__ b, TOUT* __restrict__ Y, int D)
{
    long row = blockIdx.x;
    const float4* x4 = (const float4*)(X + row * (long)D);
    const float4* g4 = (const float4*)g;
    const float4* b4 = (const float4*)b;
    int n4 = D >> 2;

    float s = 0.0f, s2 = 0.0f;
    for (int i = threadIdx.x; i < n4; i += 256) {
        float4 v = x4[i];
        s  += v.x + v.y + v.z + v.w;
        s2 += v.x * v.x + v.y * v.y + v.z * v.z + v.w * v.w;
    }
#pragma unroll
    for (int o = 16; o; o >>= 1) {
        s  += __shfl_xor_sync(0xffffffffu, s, o);
        s2 += __shfl_xor_sync(0xffffffffu, s2, o);
    }
    __shared__ float sh[16];
    int w = threadIdx.x >> 5, lane = threadIdx.x & 31;
    if (lane == 0) { sh[w] = s; sh[w + 8] = s2; }
    __syncthreads();
    if (threadIdx.x < 32) {
        float a = (threadIdx.x < 8) ? sh[threadIdx.x] : 0.0f;
        float c = (threadIdx.x < 8) ? sh[threadIdx.x + 8] : 0.0f;
#pragma unroll
        for (int o = 16; o; o >>= 1) {
            a += __shfl_xor_sync(0xffffffffu, a, o);
            c += __shfl_xor_sync(0xffffffffu, c, o);
        }
        if (threadIdx.x == 0) { sh[0] = a; sh[1] = c; }
    }
    __syncthreads();
    float invD = 1.0f / (float)D;
    float mu   = sh[0] * invD;
    float var  = sh[1] * invD - mu * mu;
    float rstd = rsqrtf(var + EPSF);

    for (int i = threadIdx.x; i < n4; i += 256) {
        float4 v = x4[i], gg = g4[i], bb = b4[i];
        v.x = (v.x - mu) * rstd * gg.x + bb.x;
        v.y = (v.y - mu) * rstd * gg.y + bb.y;
        v.z = (v.z - mu) * rstd * gg.z + bb.z;
        v.w = (v.w - mu) * rstd * gg.w + bb.w;
        if (sizeof(TOUT) == 4) {
            ((float4*)(void*)(Y + row * (long)D))[i] = v;
        } else {
            uint2 u = { pack2(v.x, v.y), pack2(v.z, v.w) };
            ((uint2*)(void*)(Y + row * (long)D))[i] = u;
        }
    }
}

// ---------------- launch ----------------
extern "C" void kernel_launch(void* const* d_in, const int* in_sizes, int n_in,
                              void* d_out, int out_size)
{
    const float* grid      = (const float*)d_in[0];
    const float* query_pos = (const float*)d_in[1];
    const float* Wq        = (const float*)d_in[2];
    const float* Wk        = (const float*)d_in[3];
    const float* Wv        = (const float*)d_in[4];
    const float* Wo        = (const float*)d_in[5];
    const float* lng_g     = (const float*)d_in[6];
    const float* lng_b     = (const float*)d_in[7];
    const float* lnq_g     = (const float*)d_in[8];
    const float* lnq_b     = (const float*)d_in[9];
    const float* lnm_g     = (const float*)d_in[10];
    const float* lnm_b     = (const float*)d_in[11];
    const float* W1        = (const float*)d_in[12];
    const float* b1        = (const float*)d_in[13];
    const float* W2        = (const float*)d_in[14];
    const float* b2        = (const float*)d_in[15];
    float* out = (float*)d_out;

    float *Kp, *V, *Q, *x;
    __half *gridh, *Kn, *qn, *attn, *xn, *hb;
    __half *WkT, *WvT, *WqT, *WoT, *W1T, *W2T, *VT;
    cudaGetSymbolAddress((void**)&gridh, g_gridh);
    cudaGetSymbolAddress((void**)&Kp,   g_Kpre);
    cudaGetSymbolAddress((void**)&Kn,   g_Kn);
    cudaGetSymbolAddress((void**)&V,    g_V);
    cudaGetSymbolAddress((void**)&qn,   g_qn);
    cudaGetSymbolAddress((void**)&Q,    g_Q);
    cudaGetSymbolAddress((void**)&attn, g_attn);
    cudaGetSymbolAddress((void**)&x,    g_x);
    cudaGetSymbolAddress((void**)&xn,   g_xn);
    cudaGetSymbolAddress((void**)&hb,   g_h);
    cudaGetSymbolAddress((void**)&WkT,  g_WkT);
    cudaGetSymbolAddress((void**)&WvT,  g_WvT);
    cudaGetSymbolAddress((void**)&WqT,  g_WqT);
    cudaGetSymbolAddress((void**)&WoT,  g_WoT);
    cudaGetSymbolAddress((void**)&W1T,  g_W1T);
    cudaGetSymbolAddress((void**)&W2T,  g_W2T);
    cudaGetSymbolAddress((void**)&VT,   g_VT);

    cudaFuncSetAttribute(fused_attn,
        cudaFuncAttributeMaxDynamicSharedMemorySize, FA_SMEM);

    dim3 blk(256);
    const int MG = BB * TKV;       // 4096
    const int MQ = BB * LQ;        // 16384
    const int HD = MULT * SEQ_D;   // 4096

    // 0) fp16 conversions / transposes
    f2h_kernel<<<(MG * GRID_D) / (256 * 8), blk>>>(grid, gridh);
    transpose_kernel<<<dim3(SEQ_D / 32, GRID_D / 32), blk>>>(Wk, WkT, GRID_D, SEQ_D);
    transpose_kernel<<<dim3(SEQ_D / 32, GRID_D / 32), blk>>>(Wv, WvT, GRID_D, SEQ_D);
    transpose_kernel<<<dim3(SEQ_D / 32, POS_D / 32),  blk>>>(Wq, WqT, POS_D, SEQ_D);
    transpose_kernel<<<dim3(SEQ_D / 32, SEQ_D / 32),  blk>>>(Wo, WoT, SEQ_D, SEQ_D);
    transpose_kernel<<<dim3(HD / 32, SEQ_D / 32),     blk>>>(W1, W1T, SEQ_D, HD);
    transpose_kernel<<<dim3(SEQ_D / 32, HD / 32),     blk>>>(W2, W2T, HD, SEQ_D);

    // 1) Kpre = grid @ Wk ; V = grid @ Wv
    gemm_h<float, EPI_NONE, 128><<<dim3(SEQ_D / 128, MG / 128), blk>>>(
        gridh, WkT, nullptr, nullptr, Kp, MG, SEQ_D, GRID_D,
        GRID_D, GRID_D, SEQ_D, 1.0f);
    gemm_h<float, EPI_NONE, 128><<<dim3(SEQ_D / 128, MG / 128), blk>>>(
        gridh, WvT, nullptr, nullptr, V, MG, SEQ_D, GRID_D,
        GRID_D, GRID_D, SEQ_D, 1.0f);

    // 1b) VT = per-head transpose of V (fp16)
    vt_kernel<<<dim3(TKV / 32, HEAD / 32, BB * NH), blk>>>(V, VT);

    // 2) Kn = LN(Kpre) -> fp16 ; qn = LN(query_pos) -> fp16
    ln_kernel<__half><<<MG, 256>>>(Kp, lng_g, lng_b, Kn, SEQ_D);
    ln_kernel<__half><<<MQ, 256>>>(query_pos, lnq_g, lnq_b, qn, POS_D);

    // 3) Q = qn @ Wq  (fp32 out, needed as residual)
    gemm_h<float, EPI_NONE, 128><<<dim3(SEQ_D / 128, MQ / 128), blk>>>(
        qn, WqT, nullptr, nullptr, Q, MQ, SEQ_D, POS_D,
        POS_D, POS_D, SEQ_D, 1.0f);

    // 4-6) fused attention -> attn fp16
    fused_attn<<<dim3(LQ / 128, BB * NH), blk, FA_SMEM>>>(Q, Kn, VT, attn);

    // 7) x = Q + attn @ Wo
    gemm_h<float, EPI_RESID, 128><<<dim3(SEQ_D / 128, MQ / 128), blk>>>(
        attn, WoT, nullptr, Q, x, MQ, SEQ_D, SEQ_D,
        SEQ_D, SEQ_D, SEQ_D, 1.0f);

    // 8) xn = LN(x) -> fp16
    ln_kernel<__half><<<MQ, 256>>>(x, lnm_g, lnm_b, xn, SEQ_D);

    // 9) hb = gelu(xn @ W1 + b1) -> fp16
    gemm_h<__half, EPI_GELU_BIAS, 128><<<dim3(HD / 128, MQ / 128), blk>>>(
        xn, W1T, b1, nullptr, hb, MQ, HD, SEQ_D,
        SEQ_D, SEQ_D, HD, 1.0f);

    // 10) out = x + hb @ W2 + b2
    gemm_h<float, EPI_BIAS_RESID, 128><<<dim3(SEQ_D / 128, MQ / 128), blk>>>(
        hb, W2T, b2, x, out, MQ, SEQ_D, HD,
        HD, HD, SEQ_D, 1.0f);
}